// round 11
// baseline (speedup 1.0000x reference)
#include <cuda_runtime.h>
#include <cuda_fp16.h>
#include <math.h>
#include <stdint.h>

// ---------------- scratch (device globals) ---------------------------------------
__device__ __half g_hh[26214400];          // conv1 out fp16, [b][pos400][ci256]
__device__ __half g_whi[5308416];          // prim weights hi fp16, [tap81][co256][ci256]
__device__ __half g_wlo[5308416];          // prim weights lo fp16
__device__ float g_x3[256 * 1152 * 8];     // squashed primary caps [b][i][a]
__device__ __half g_votes[47185920];       // votes fp16 [i][b][ot]
__device__ float g_r1[256 * 512];
__device__ float g_r2[256 * 1024];

// ---------------- f32x2 helpers ---------------------------------------------------
__device__ __forceinline__ unsigned long long pk2(float lo, float hi) {
    unsigned long long r;
    asm("mov.b64 %0, {%1, %2};" : "=l"(r) : "f"(lo), "f"(hi));
    return r;
}
__device__ __forceinline__ void fma2(unsigned long long& d, unsigned long long a,
                                     unsigned long long b) {
    asm("fma.rn.f32x2 %0, %1, %2, %0;" : "+l"(d) : "l"(a), "l"(b));
}
__device__ __forceinline__ float2 upk2(unsigned long long v) {
    float2 f;
    asm("mov.b64 {%0, %1}, %2;" : "=f"(f.x), "=f"(f.y) : "l"(v));
    return f;
}

// ---------------- baseline-PTX helpers --------------------------------------------
__device__ __forceinline__ uint32_t smem_to_u32(const void* p) {
    uint32_t a;
    asm("{ .reg .u64 t; cvta.to.shared.u64 t, %1; cvt.u32.u64 %0, t; }" : "=r"(a) : "l"(p));
    return a;
}
__device__ __forceinline__ void cpa16(uint32_t s, const void* g) {
    asm volatile("cp.async.cg.shared.global [%0], [%1], 16;" :: "r"(s), "l"(g));
}
#define CP_COMMIT() asm volatile("cp.async.commit_group;" ::: "memory")
#define CP_WAIT0()  asm volatile("cp.async.wait_group 0;" ::: "memory")
#define CP_WAIT1()  asm volatile("cp.async.wait_group 1;" ::: "memory")

__device__ __forceinline__ void ldm_x4(uint32_t& r0, uint32_t& r1, uint32_t& r2,
                                       uint32_t& r3, uint32_t a) {
    asm volatile("ldmatrix.sync.aligned.m8n8.x4.shared.b16 {%0,%1,%2,%3}, [%4];"
                 : "=r"(r0), "=r"(r1), "=r"(r2), "=r"(r3) : "r"(a));
}
__device__ __forceinline__ void ldm_x2(uint32_t& r0, uint32_t& r1, uint32_t a) {
    asm volatile("ldmatrix.sync.aligned.m8n8.x2.shared.b16 {%0,%1}, [%2];"
                 : "=r"(r0), "=r"(r1) : "r"(a));
}
__device__ __forceinline__ void mma_f16(float* c, const uint32_t* a, const uint32_t* b) {
    asm volatile("mma.sync.aligned.m16n8k16.row.col.f32.f16.f16.f32 "
                 "{%0,%1,%2,%3}, {%4,%5,%6,%7}, {%8,%9}, {%0,%1,%2,%3};"
                 : "+f"(c[0]), "+f"(c[1]), "+f"(c[2]), "+f"(c[3])
                 : "r"(a[0]), "r"(a[1]), "r"(a[2]), "r"(a[3]), "r"(b[0]), "r"(b[1]));
}
#define SWZ(x) ((x) ^ (((x) >> 3) & 0x70))

// ---------------- P0: weight split/transpose, coalesced ---------------------------
__global__ __launch_bounds__(256) void k_wsplit(const float* __restrict__ pw) {
    extern __shared__ unsigned sbuf[];   // 81*256
    int co = blockIdx.x, ci = threadIdx.x;
    const float* src = pw + co * 20736 + ci * 81;
#pragma unroll
    for (int tap = 0; tap < 81; tap++) {
        float w = src[tap];
        __half h = __float2half(w);
        __half l = __float2half(w - __half2float(h));
        sbuf[tap * 256 + ci] = (unsigned)__half_as_ushort(h) |
                               ((unsigned)__half_as_ushort(l) << 16);
    }
    __syncthreads();
    for (int e = ci; e < 81 * 256; e += 256) {
        int tap = e >> 8, c2 = e & 255;
        unsigned v = sbuf[e];
        g_whi[tap * 65536 + co * 256 + c2] = __ushort_as_half((unsigned short)(v & 0xffff));
        g_wlo[tap * 65536 + co * 256 + c2] = __ushort_as_half((unsigned short)(v >> 16));
    }
}

// ---------------- K1: conv1 9x9 s1 + bias + relu -> fp16 [b][pos][ci] -------------
__global__ __launch_bounds__(400) void k_conv1(const float* __restrict__ x,
                                               const float* __restrict__ w,
                                               const float* __restrict__ bias) {
    int b = blockIdx.y, c0 = blockIdx.x * 32;
    __shared__ float img[784];
    __shared__ float ws[32 * 81];
    __shared__ float bs[32];
    __shared__ unsigned short spk[100 * 32];
    int t = threadIdx.x;
    for (int e = t; e < 784; e += 400) img[e] = x[b * 784 + e];
    for (int e = t; e < 2592; e += 400) ws[e] = w[c0 * 81 + e];
    if (t < 32) bs[t] = bias[c0 + t];
    __syncthreads();

    int pg = t % 100, chg = t / 100;
    int p0 = pg * 4;
    int oy = p0 / 20, ox0 = p0 % 20;

    unsigned long long acc2[4][4];
#pragma unroll
    for (int p = 0; p < 4; p++)
#pragma unroll
        for (int j = 0; j < 4; j++) acc2[p][j] = 0ull;

    for (int kh = 0; kh < 9; kh++) {
        const float* row = img + (oy + kh) * 28 + ox0;
        float xw[12];
#pragma unroll
        for (int i = 0; i < 12; i++) xw[i] = row[i];
#pragma unroll
        for (int kw = 0; kw < 9; kw++) {
            unsigned long long xp[4];
#pragma unroll
            for (int j = 0; j < 4; j++) xp[j] = pk2(xw[kw + j], xw[kw + j]);
#pragma unroll
            for (int p = 0; p < 4; p++) {
                unsigned long long wp = pk2(ws[(chg * 8 + 2 * p) * 81 + kh * 9 + kw],
                                            ws[(chg * 8 + 2 * p + 1) * 81 + kh * 9 + kw]);
#pragma unroll
                for (int j = 0; j < 4; j++) fma2(acc2[p][j], xp[j], wp);
            }
        }
    }

    unsigned short pkv[8][4];
#pragma unroll
    for (int p = 0; p < 4; p++) {
        float b0v = bs[chg * 8 + 2 * p], b1v = bs[chg * 8 + 2 * p + 1];
#pragma unroll
        for (int j = 0; j < 4; j++) {
            float2 f = upk2(acc2[p][j]);
            pkv[2 * p][j] = __half_as_ushort(__float2half(fmaxf(f.x + b0v, 0.f)));
            pkv[2 * p + 1][j] = __half_as_ushort(__float2half(fmaxf(f.y + b1v, 0.f)));
        }
    }
    for (int c = 0; c < 4; c++) {
        if (pg >= c * 25 && pg < c * 25 + 25) {
            int pl = p0 - c * 100;
#pragma unroll
            for (int ch = 0; ch < 8; ch++)
#pragma unroll
                for (int j = 0; j < 4; j++)
                    spk[(pl + j) * 32 + chg * 8 + ch] = pkv[ch][j];
        }
        __syncthreads();
        for (int e = t; e < 3200; e += 400) {
            int pl = e >> 5, ch = e & 31;
            g_hh[(b * 400 + c * 100 + pl) * 256 + c0 + ch] = __ushort_as_half(spk[e]);
        }
        __syncthreads();
    }
}

// ---------------- K2: primary-caps conv, fp16 2-term split, 3-stage ring ----------
// grid (2 co-halves of 128, 64 b-groups of 4), 256 thr = 8 warps (4M x 2N).
// CTA tile: M=128 co, N=144, K = 81 taps x 4 ci-blocks(64) = 324 stages.
// 3-deep cp.async ring: wait_group 1 -> staging latency spans two stages.
static constexpr int PRIM_NS = 324;

__global__ __launch_bounds__(256, 1) void k_prim(const float* __restrict__ pb) {
    extern __shared__ char sm[];
    uint32_t sb = smem_to_u32(sm);
    const int t = threadIdx.x, wid = t >> 5, lane = t & 31;
    const int co0 = blockIdx.x * 128;
    const int b0 = blockIdx.y * 4;
    const int warpM = wid >> 1, warpN = wid & 1;

    // ring of 3 buffers, each 51200B: AH +0 (16K), AL +16384 (16K), BH +32768 (18K)
    const uint32_t BASE[3] = {0u, 51200u, 102400u};

    uint32_t a_sm[4]; long a_g[4];
#pragma unroll
    for (int k = 0; k < 4; k++) {
        int e = t + k * 256, row = e >> 3, q = e & 7;
        a_sm[k] = SWZ((uint32_t)(row * 128 + q * 16));
        a_g[k] = (long)(co0 + row) * 256 + q * 8;
    }
    uint32_t b_sm[5]; long b_g[5]; bool b_p[5];
#pragma unroll
    for (int k = 0; k < 5; k++) {
        int e = t + k * 256;
        b_p[k] = (e < 1152);
        int n = e >> 3, q = e & 7;
        if (!b_p[k]) { n = 0; q = 0; }
        int bb = n / 36, sp = n % 36, oy = sp / 6, ox = sp % 6;
        b_sm[k] = SWZ((uint32_t)(n * 128 + q * 16));
        b_g[k] = (long)((b0 + bb) * 400 + oy * 40 + ox * 2) * 256 + q * 8;
    }

    auto stage = [&](int buf, int s) {
        int tap = s >> 2, cb = s & 3;
        long wofs = (long)tap * 65536 + cb * 64;
        long xofs = (long)((tap / 9) * 20 + (tap % 9)) * 256 + cb * 64;
        uint32_t base = sb + BASE[buf];
#pragma unroll
        for (int k = 0; k < 4; k++) {
            cpa16(base + a_sm[k], g_whi + wofs + a_g[k]);
            cpa16(base + 16384u + a_sm[k], g_wlo + wofs + a_g[k]);
        }
#pragma unroll
        for (int k = 0; k < 5; k++)
            if (b_p[k]) cpa16(base + 32768u + b_sm[k], g_hh + xofs + b_g[k]);
        CP_COMMIT();
    };

    float acc[2][9][4];
#pragma unroll
    for (int mt = 0; mt < 2; mt++)
#pragma unroll
        for (int nt = 0; nt < 9; nt++)
#pragma unroll
            for (int j = 0; j < 4; j++) acc[mt][nt][j] = 0.f;

    const int arow = warpM * 32 + (lane & 15);
    const int n0w = warpN * 72;
    const int csel = (lane >> 4) * 16;

    uint32_t ahf[2][2][4], alf[2][2][4], bhf[2][9][2];

    stage(0, 0);
    stage(1, 1);

    for (int s = 0; s < PRIM_NS; s++) {
        if (s >= PRIM_NS - 1) { CP_WAIT0(); } else { CP_WAIT1(); }
        __syncthreads();
        if (s + 2 < PRIM_NS) stage((s + 2) % 3, s + 2);

        uint32_t base = sb + BASE[s % 3];
        uint32_t bA_h = base, bA_l = base + 16384u, bB_h = base + 32768u;

#define LOADFRAG(PB, KS) do { \
        int kb_ = (KS) * 32; \
        uint32_t oa0_ = SWZ((uint32_t)(arow * 128 + kb_ + csel)); \
        uint32_t oa1_ = SWZ((uint32_t)((arow + 16) * 128 + kb_ + csel)); \
        ldm_x4(ahf[PB][0][0], ahf[PB][0][1], ahf[PB][0][2], ahf[PB][0][3], bA_h + oa0_); \
        ldm_x4(ahf[PB][1][0], ahf[PB][1][1], ahf[PB][1][2], ahf[PB][1][3], bA_h + oa1_); \
        ldm_x4(alf[PB][0][0], alf[PB][0][1], alf[PB][0][2], alf[PB][0][3], bA_l + oa0_); \
        ldm_x4(alf[PB][1][0], alf[PB][1][1], alf[PB][1][2], alf[PB][1][3], bA_l + oa1_); \
        _Pragma("unroll") \
        for (int p_ = 0; p_ < 4; p_++) { \
            uint32_t ob_ = SWZ((uint32_t)((n0w + p_ * 16 + (lane & 15)) * 128 + kb_ + csel)); \
            ldm_x4(bhf[PB][2 * p_][0], bhf[PB][2 * p_ + 1][0], \
                   bhf[PB][2 * p_][1], bhf[PB][2 * p_ + 1][1], bB_h + ob_); \
        } \
        { uint32_t ob2_ = SWZ((uint32_t)((n0w + 64 + (lane & 7)) * 128 + kb_ + \
                                         ((lane >> 3) & 1) * 16)); \
          ldm_x2(bhf[PB][8][0], bhf[PB][8][1], bB_h + ob2_); } \
    } while (0)

        LOADFRAG(0, 0);
#pragma unroll
        for (int ks = 0; ks < 4; ks++) {
            if (ks == 0) LOADFRAG(1, 1);
            else if (ks == 1) LOADFRAG(0, 2);
            else if (ks == 2) LOADFRAG(1, 3);
            const int fb = ks & 1;
#pragma unroll
            for (int mt = 0; mt < 2; mt++)
#pragma unroll
                for (int nt = 0; nt < 9; nt++) {
                    mma_f16(acc[mt][nt], ahf[fb][mt], bhf[fb][nt]);
                    mma_f16(acc[mt][nt], alf[fb][mt], bhf[fb][nt]);
                }
        }
#undef LOADFRAG
    }

    // epilogue: /32 + bias, squash over 8 atoms (lanes xor 4,8,16), write x3
    int atom = lane >> 2;
#pragma unroll
    for (int mt = 0; mt < 2; mt++) {
        int cobase = co0 + warpM * 32 + mt * 16;
        float bv0 = pb[cobase + atom];
        float bv1 = pb[cobase + 8 + atom];
        int cap0 = (cobase >> 3);
#pragma unroll
        for (int nt = 0; nt < 9; nt++) {
            float pr0 = acc[mt][nt][0] * (1.f / 32.f) + bv0;
            float pr1 = acc[mt][nt][1] * (1.f / 32.f) + bv0;
            float pr2 = acc[mt][nt][2] * (1.f / 32.f) + bv1;
            float pr3 = acc[mt][nt][3] * (1.f / 32.f) + bv1;
            float s0 = pr0 * pr0, s1 = pr1 * pr1, s2 = pr2 * pr2, s3 = pr3 * pr3;
#pragma unroll
            for (int d = 4; d <= 16; d <<= 1) {
                s0 += __shfl_xor_sync(0xffffffffu, s0, d);
                s1 += __shfl_xor_sync(0xffffffffu, s1, d);
                s2 += __shfl_xor_sync(0xffffffffu, s2, d);
                s3 += __shfl_xor_sync(0xffffffffu, s3, d);
            }
            float c0 = (s0 / (1.f + s0)) * rsqrtf(s0 + 1e-9f);
            float c1 = (s1 / (1.f + s1)) * rsqrtf(s1 + 1e-9f);
            float c2 = (s2 / (1.f + s2)) * rsqrtf(s2 + 1e-9f);
            float c3 = (s3 / (1.f + s3)) * rsqrtf(s3 + 1e-9f);
            int ncol = n0w + nt * 8 + (lane & 3) * 2;
            int bb = b0 + ncol / 36, sp = ncol % 36;
            float* base = g_x3 + bb * 9216;
            base[(cap0 * 36 + sp) * 8 + atom] = pr0 * c0;
            base[(cap0 * 36 + sp + 1) * 8 + atom] = pr1 * c1;
            base[((cap0 + 1) * 36 + sp) * 8 + atom] = pr2 * c2;
            base[((cap0 + 1) * 36 + sp + 1) * 8 + atom] = pr3 * c3;
        }
    }
}

// ---------------- K3: votes [i][b][ot] fp16, block per i ---------------------------
__global__ __launch_bounds__(256) void k_votes(const float* __restrict__ dw) {
    int i = blockIdx.x, t = threadIdx.x;    // t = b
    __shared__ float ws[1280];
    __shared__ float stg[256 * 17];
    for (int e = t; e < 1280; e += 256) ws[e] = dw[i * 1280 + e];
    const float4* xp = (const float4*)(g_x3 + t * 9216 + i * 8);
    float4 a0 = xp[0], a1 = xp[1];
    float xv[8] = {a0.x, a0.y, a0.z, a0.w, a1.x, a1.y, a1.z, a1.w};
    unsigned long long xpk[8];
#pragma unroll
    for (int a = 0; a < 8; a++) xpk[a] = pk2(xv[a], xv[a]);
    __syncthreads();
    __half2* orow2 = (__half2*)(g_votes + (long)i * 40960);
    for (int c = 0; c < 160; c += 16) {
        unsigned long long acc[8];
#pragma unroll
        for (int g = 0; g < 8; g++) acc[g] = 0ull;
#pragma unroll
        for (int a = 0; a < 8; a++) {
            const float2* wp = (const float2*)(ws + a * 160 + c);
#pragma unroll
            for (int g = 0; g < 8; g++) {
                float2 wv = wp[g];
                fma2(acc[g], xpk[a], pk2(wv.x, wv.y));
            }
        }
#pragma unroll
        for (int g = 0; g < 8; g++) {
            float2 f = upk2(acc[g]);
            stg[t * 17 + 2 * g] = f.x;
            stg[t * 17 + 2 * g + 1] = f.y;
        }
        __syncthreads();
        for (int e = t; e < 2048; e += 256) {
            int b = e >> 3, j = e & 7;
            orow2[b * 80 + (c >> 1) + j] =
                __floats2half2_rn(stg[b * 17 + 2 * j], stg[b * 17 + 2 * j + 1]);
        }
        __syncthreads();
    }
}

// ---------------- K4: fused 3-iteration routing (fp16 votes) -----------------------
__global__ __launch_bounds__(512) void k_route(const float* __restrict__ db,
                                               float* __restrict__ out_digit) {
    int b = blockIdx.x, t = threadIdx.x;
    int w = t >> 5, l = t & 31;
    __shared__ float act[160], asum[160], pre[160];
    __shared__ float red[16 * 160];
    const __half* V = g_votes + b * 160;

    {
        float p0[5] = {0.f, 0.f, 0.f, 0.f, 0.f};
        for (int i = w; i < 1152; i += 16) {
            const __half* vp = V + (long)i * 40960;
#pragma unroll
            for (int k = 0; k < 5; k++) p0[k] += __half2float(vp[32 * k + l]);
        }
#pragma unroll
        for (int k = 0; k < 5; k++) red[w * 160 + 32 * k + l] = p0[k];
    }
    __syncthreads();
    if (t < 160) {
        float s = 0.f;
#pragma unroll
        for (int ww = 0; ww < 16; ww++) s += red[ww * 160 + t];
        pre[t] = 0.1f * s + db[t];
    }
    __syncthreads();
    if (t < 160) {
        int o = t >> 4;
        float n2 = 0.f;
#pragma unroll
        for (int k = 0; k < 16; k++) { float v = pre[o * 16 + k]; n2 = fmaf(v, v, n2); }
        float a = pre[t] * (n2 / (1.f + n2)) * rsqrtf(n2 + 1e-9f);
        act[t] = a; asum[t] = a;
    }
    __syncthreads();

    for (int pass = 1; pass <= 2; pass++) {
        float pacc[5] = {0.f, 0.f, 0.f, 0.f, 0.f};
        for (int i = w; i < 1152; i += 16) {
            const __half* vp = V + (long)i * 40960;
            float v[5], d[5];
#pragma unroll
            for (int k = 0; k < 5; k++) v[k] = __half2float(vp[32 * k + l]);
#pragma unroll
            for (int k = 0; k < 5; k++) {
                float s = v[k] * asum[32 * k + l];
                s += __shfl_xor_sync(0xffffffffu, s, 1);
                s += __shfl_xor_sync(0xffffffffu, s, 2);
                s += __shfl_xor_sync(0xffffffffu, s, 4);
                s += __shfl_xor_sync(0xffffffffu, s, 8);
                d[k] = s;
            }
            float dn[5];
#pragma unroll
            for (int k = 0; k < 5; k++) dn[k] = __shfl_xor_sync(0xffffffffu, d[k], 16);
            float m = -1e30f;
#pragma unroll
            for (int k = 0; k < 5; k++) m = fmaxf(m, fmaxf(d[k], dn[k]));
            float sum = 0.f, e[5];
#pragma unroll
            for (int k = 0; k < 5; k++) {
                e[k] = __expf(d[k] - m); sum += e[k];
                sum += __expf(dn[k] - m);
            }
            float inv = 1.f / sum;
#pragma unroll
            for (int k = 0; k < 5; k++) pacc[k] = fmaf(e[k] * inv, v[k], pacc[k]);
        }
#pragma unroll
        for (int k = 0; k < 5; k++) red[w * 160 + 32 * k + l] = pacc[k];
        __syncthreads();
        if (t < 160) {
            float s = 0.f;
#pragma unroll
            for (int ww = 0; ww < 16; ww++) s += red[ww * 160 + t];
            pre[t] = s + db[t];
        }
        __syncthreads();
        if (t < 160) {
            int o = t >> 4;
            float n2 = 0.f;
#pragma unroll
            for (int k = 0; k < 16; k++) { float v = pre[o * 16 + k]; n2 = fmaf(v, v, n2); }
            float a = pre[t] * (n2 / (1.f + n2)) * rsqrtf(n2 + 1e-9f);
            act[t] = a;
            if (pass == 1) asum[t] += a;
        }
        __syncthreads();
    }
    if (t < 160) out_digit[b * 160 + t] = act[t];
}

// ---------------- K5: reconstruction MLP -------------------------------------------
__global__ __launch_bounds__(512) void k_fc1(const float* __restrict__ w1,
                                             const float* __restrict__ b1,
                                             const float* __restrict__ y,
                                             const float* __restrict__ digit) {
    int b = blockIdx.x, t = threadIdx.x;
    __shared__ float m[160];
    if (t < 160) m[t] = digit[b * 160 + t] * y[b * 10 + (t >> 4)];
    __syncthreads();
    float acc = b1[t];
#pragma unroll 8
    for (int k = 0; k < 160; k++) acc = fmaf(m[k], w1[k * 512 + t], acc);
    g_r1[b * 512 + t] = fmaxf(acc, 0.f);
}

__global__ __launch_bounds__(1024) void k_fc2(const float* __restrict__ w2,
                                              const float* __restrict__ b2) {
    int b0 = blockIdx.x * 4, t = threadIdx.x;
    __shared__ float m[4][512];
    for (int e = t; e < 2048; e += 1024)
        m[e >> 9][e & 511] = g_r1[(b0 + (e >> 9)) * 512 + (e & 511)];
    __syncthreads();
    float bb = b2[t];
    float a0 = bb, a1 = bb, a2 = bb, a3 = bb;
#pragma unroll 8
    for (int k = 0; k < 512; k++) {
        float wv = w2[k * 1024 + t];
        a0 = fmaf(m[0][k], wv, a0);
        a1 = fmaf(m[1][k], wv, a1);
        a2 = fmaf(m[2][k], wv, a2);
        a3 = fmaf(m[3][k], wv, a3);
    }
    g_r2[b0 * 1024 + t] = fmaxf(a0, 0.f);
    g_r2[(b0 + 1) * 1024 + t] = fmaxf(a1, 0.f);
    g_r2[(b0 + 2) * 1024 + t] = fmaxf(a2, 0.f);
    g_r2[(b0 + 3) * 1024 + t] = fmaxf(a3, 0.f);
}

__global__ __launch_bounds__(784) void k_fc3(const float* __restrict__ w3,
                                             const float* __restrict__ b3,
                                             float* __restrict__ recon) {
    int b0 = blockIdx.x * 4, t = threadIdx.x;
    __shared__ float m[4][1024];
    for (int e = t; e < 4096; e += 784)
        m[e >> 10][e & 1023] = g_r2[(b0 + (e >> 10)) * 1024 + (e & 1023)];
    __syncthreads();
    float bb = b3[t];
    float a0 = bb, a1 = bb, a2 = bb, a3 = bb;
#pragma unroll 8
    for (int k = 0; k < 1024; k++) {
        float wv = w3[k * 784 + t];
        a0 = fmaf(m[0][k], wv, a0);
        a1 = fmaf(m[1][k], wv, a1);
        a2 = fmaf(m[2][k], wv, a2);
        a3 = fmaf(m[3][k], wv, a3);
    }
    recon[b0 * 784 + t] = 1.f / (1.f + __expf(-a0));
    recon[(b0 + 1) * 784 + t] = 1.f / (1.f + __expf(-a1));
    recon[(b0 + 2) * 784 + t] = 1.f / (1.f + __expf(-a2));
    recon[(b0 + 3) * 784 + t] = 1.f / (1.f + __expf(-a3));
}

// ---------------- launch ------------------------------------------------------------
extern "C" void kernel_launch(void* const* d_in, const int* in_sizes, int n_in,
                              void* d_out, int out_size) {
    const float* x   = (const float*)d_in[0];
    const float* y   = (const float*)d_in[1];
    const float* c1w = (const float*)d_in[2];
    const float* c1b = (const float*)d_in[3];
    const float* pw  = (const float*)d_in[4];
    const float* pb  = (const float*)d_in[5];
    const float* dw  = (const float*)d_in[6];
    const float* db  = (const float*)d_in[7];
    const float* w1  = (const float*)d_in[8];
    const float* b1  = (const float*)d_in[9];
    const float* w2  = (const float*)d_in[10];
    const float* b2  = (const float*)d_in[11];
    const float* w3  = (const float*)d_in[12];
    const float* b3  = (const float*)d_in[13];
    float* out = (float*)d_out;   // digit [0,40960), recon [40960,241664)

    cudaFuncSetAttribute(k_prim, cudaFuncAttributeMaxDynamicSharedMemorySize, 153600);
    cudaFuncSetAttribute(k_wsplit, cudaFuncAttributeMaxDynamicSharedMemorySize, 82944);

    k_wsplit<<<256, 256, 82944>>>(pw);
    k_conv1<<<dim3(8, 256), 400>>>(x, c1w, c1b);
    k_prim<<<dim3(2, 64), 256, 153600>>>(pb);
    k_votes<<<1152, 256>>>(dw);
    k_route<<<256, 512>>>(db, out);
    k_fc1<<<256, 512>>>(w1, b1, y, out);
    k_fc2<<<64, 1024>>>(w2, b2);
    k_fc3<<<64, 784>>>(w3, b3, out + 40960);
}

// round 12
// speedup vs baseline: 1.0745x; 1.0745x over previous
#include <cuda_runtime.h>
#include <cuda_fp16.h>
#include <math.h>
#include <stdint.h>

// ---------------- scratch (device globals) ---------------------------------------
__device__ __half g_hh[26214400];          // conv1 out fp16, [b][pos400][ci256]
__device__ __half g_whi[5308416];          // prim weights hi fp16, [tap81][co256][ci256]
__device__ __half g_wlo[5308416];          // prim weights lo fp16
__device__ float g_x3[256 * 1152 * 8];     // squashed primary caps [b][i][a]
__device__ __half g_votes[47185920];       // votes fp16 [i][b][ot]
__device__ float g_r1[256 * 512];
__device__ float g_r2[256 * 1024];

// ---------------- f32x2 helpers ---------------------------------------------------
__device__ __forceinline__ unsigned long long pk2(float lo, float hi) {
    unsigned long long r;
    asm("mov.b64 %0, {%1, %2};" : "=l"(r) : "f"(lo), "f"(hi));
    return r;
}
__device__ __forceinline__ void fma2(unsigned long long& d, unsigned long long a,
                                     unsigned long long b) {
    asm("fma.rn.f32x2 %0, %1, %2, %0;" : "+l"(d) : "l"(a), "l"(b));
}
__device__ __forceinline__ float2 upk2(unsigned long long v) {
    float2 f;
    asm("mov.b64 {%0, %1}, %2;" : "=f"(f.x), "=f"(f.y) : "l"(v));
    return f;
}

// ---------------- baseline-PTX helpers --------------------------------------------
__device__ __forceinline__ uint32_t smem_to_u32(const void* p) {
    uint32_t a;
    asm("{ .reg .u64 t; cvta.to.shared.u64 t, %1; cvt.u32.u64 %0, t; }" : "=r"(a) : "l"(p));
    return a;
}
__device__ __forceinline__ void cpa16(uint32_t s, const void* g) {
    asm volatile("cp.async.cg.shared.global [%0], [%1], 16;" :: "r"(s), "l"(g));
}
#define CP_COMMIT() asm volatile("cp.async.commit_group;" ::: "memory")
#define CP_WAIT0()  asm volatile("cp.async.wait_group 0;" ::: "memory")

__device__ __forceinline__ void ldm_x4(uint32_t& r0, uint32_t& r1, uint32_t& r2,
                                       uint32_t& r3, uint32_t a) {
    asm volatile("ldmatrix.sync.aligned.m8n8.x4.shared.b16 {%0,%1,%2,%3}, [%4];"
                 : "=r"(r0), "=r"(r1), "=r"(r2), "=r"(r3) : "r"(a));
}
__device__ __forceinline__ void ldm_x2(uint32_t& r0, uint32_t& r1, uint32_t a) {
    asm volatile("ldmatrix.sync.aligned.m8n8.x2.shared.b16 {%0,%1}, [%2];"
                 : "=r"(r0), "=r"(r1) : "r"(a));
}
__device__ __forceinline__ void mma_f16(float* c, const uint32_t* a, const uint32_t* b) {
    asm volatile("mma.sync.aligned.m16n8k16.row.col.f32.f16.f16.f32 "
                 "{%0,%1,%2,%3}, {%4,%5,%6,%7}, {%8,%9}, {%0,%1,%2,%3};"
                 : "+f"(c[0]), "+f"(c[1]), "+f"(c[2]), "+f"(c[3])
                 : "r"(a[0]), "r"(a[1]), "r"(a[2]), "r"(a[3]), "r"(b[0]), "r"(b[1]));
}
#define SWZ(x) ((x) ^ (((x) >> 3) & 0x70))

// ---------------- P0: weight split/transpose, coalesced ---------------------------
__global__ __launch_bounds__(256) void k_wsplit(const float* __restrict__ pw) {
    extern __shared__ unsigned sbuf[];   // 81*256
    int co = blockIdx.x, ci = threadIdx.x;
    const float* src = pw + co * 20736 + ci * 81;
#pragma unroll
    for (int tap = 0; tap < 81; tap++) {
        float w = src[tap];
        __half h = __float2half(w);
        __half l = __float2half(w - __half2float(h));
        sbuf[tap * 256 + ci] = (unsigned)__half_as_ushort(h) |
                               ((unsigned)__half_as_ushort(l) << 16);
    }
    __syncthreads();
    for (int e = ci; e < 81 * 256; e += 256) {
        int tap = e >> 8, c2 = e & 255;
        unsigned v = sbuf[e];
        g_whi[tap * 65536 + co * 256 + c2] = __ushort_as_half((unsigned short)(v & 0xffff));
        g_wlo[tap * 65536 + co * 256 + c2] = __ushort_as_half((unsigned short)(v >> 16));
    }
}

// ---------------- K1: conv1 9x9 s1 + bias + relu -> fp16 [b][pos][ci] -------------
__global__ __launch_bounds__(400) void k_conv1(const float* __restrict__ x,
                                               const float* __restrict__ w,
                                               const float* __restrict__ bias) {
    int b = blockIdx.y, c0 = blockIdx.x * 32;
    __shared__ float img[784];
    __shared__ float ws[32 * 81];
    __shared__ float bs[32];
    __shared__ unsigned short spk[100 * 32];
    int t = threadIdx.x;
    for (int e = t; e < 784; e += 400) img[e] = x[b * 784 + e];
    for (int e = t; e < 2592; e += 400) ws[e] = w[c0 * 81 + e];
    if (t < 32) bs[t] = bias[c0 + t];
    __syncthreads();

    int pg = t % 100, chg = t / 100;
    int p0 = pg * 4;
    int oy = p0 / 20, ox0 = p0 % 20;

    unsigned long long acc2[4][4];
#pragma unroll
    for (int p = 0; p < 4; p++)
#pragma unroll
        for (int j = 0; j < 4; j++) acc2[p][j] = 0ull;

    for (int kh = 0; kh < 9; kh++) {
        const float* row = img + (oy + kh) * 28 + ox0;
        float xw[12];
#pragma unroll
        for (int i = 0; i < 12; i++) xw[i] = row[i];
#pragma unroll
        for (int kw = 0; kw < 9; kw++) {
            unsigned long long xp[4];
#pragma unroll
            for (int j = 0; j < 4; j++) xp[j] = pk2(xw[kw + j], xw[kw + j]);
#pragma unroll
            for (int p = 0; p < 4; p++) {
                unsigned long long wp = pk2(ws[(chg * 8 + 2 * p) * 81 + kh * 9 + kw],
                                            ws[(chg * 8 + 2 * p + 1) * 81 + kh * 9 + kw]);
#pragma unroll
                for (int j = 0; j < 4; j++) fma2(acc2[p][j], xp[j], wp);
            }
        }
    }

    unsigned short pkv[8][4];
#pragma unroll
    for (int p = 0; p < 4; p++) {
        float b0v = bs[chg * 8 + 2 * p], b1v = bs[chg * 8 + 2 * p + 1];
#pragma unroll
        for (int j = 0; j < 4; j++) {
            float2 f = upk2(acc2[p][j]);
            pkv[2 * p][j] = __half_as_ushort(__float2half(fmaxf(f.x + b0v, 0.f)));
            pkv[2 * p + 1][j] = __half_as_ushort(__float2half(fmaxf(f.y + b1v, 0.f)));
        }
    }
    for (int c = 0; c < 4; c++) {
        if (pg >= c * 25 && pg < c * 25 + 25) {
            int pl = p0 - c * 100;
#pragma unroll
            for (int ch = 0; ch < 8; ch++)
#pragma unroll
                for (int j = 0; j < 4; j++)
                    spk[(pl + j) * 32 + chg * 8 + ch] = pkv[ch][j];
        }
        __syncthreads();
        for (int e = t; e < 3200; e += 400) {
            int pl = e >> 5, ch = e & 31;
            g_hh[(b * 400 + c * 100 + pl) * 256 + c0 + ch] = __ushort_as_half(spk[e]);
        }
        __syncthreads();
    }
}

// ---------------- K2: primary-caps conv, fp16 2-term split (r10 double-buffer) ----
// grid (2 co-halves of 128, 64 b-groups of 4), 256 thr = 8 warps (4M x 2N).
static constexpr int PRIM_NS = 324;

__global__ __launch_bounds__(256, 1) void k_prim(const float* __restrict__ pb) {
    extern __shared__ char sm[];
    uint32_t sb = smem_to_u32(sm);
    const int t = threadIdx.x, wid = t >> 5, lane = t & 31;
    const int co0 = blockIdx.x * 128;
    const int b0 = blockIdx.y * 4;
    const int warpM = wid >> 1, warpN = wid & 1;

    // buf0: AH 0, AL 16384, BH 32768..51200 ; buf1: AH 51200, AL 67584, BH 83968..102400
    const uint32_t AH[2] = {0u, 51200u};
    const uint32_t AL[2] = {16384u, 67584u};
    const uint32_t BH[2] = {32768u, 83968u};

    uint32_t a_sm[4]; long a_g[4];
#pragma unroll
    for (int k = 0; k < 4; k++) {
        int e = t + k * 256, row = e >> 3, q = e & 7;
        a_sm[k] = SWZ((uint32_t)(row * 128 + q * 16));
        a_g[k] = (long)(co0 + row) * 256 + q * 8;
    }
    uint32_t b_sm[5]; long b_g[5]; bool b_p[5];
#pragma unroll
    for (int k = 0; k < 5; k++) {
        int e = t + k * 256;
        b_p[k] = (e < 1152);
        int n = e >> 3, q = e & 7;
        if (!b_p[k]) { n = 0; q = 0; }
        int bb = n / 36, sp = n % 36, oy = sp / 6, ox = sp % 6;
        b_sm[k] = SWZ((uint32_t)(n * 128 + q * 16));
        b_g[k] = (long)((b0 + bb) * 400 + oy * 40 + ox * 2) * 256 + q * 8;
    }

    auto stage = [&](int buf, int s) {
        int tap = s >> 2, cb = s & 3;
        long wofs = (long)tap * 65536 + cb * 64;
        long xofs = (long)((tap / 9) * 20 + (tap % 9)) * 256 + cb * 64;
#pragma unroll
        for (int k = 0; k < 4; k++) {
            cpa16(sb + AH[buf] + a_sm[k], g_whi + wofs + a_g[k]);
            cpa16(sb + AL[buf] + a_sm[k], g_wlo + wofs + a_g[k]);
        }
#pragma unroll
        for (int k = 0; k < 5; k++)
            if (b_p[k]) cpa16(sb + BH[buf] + b_sm[k], g_hh + xofs + b_g[k]);
        CP_COMMIT();
    };

    float acc[2][9][4];
#pragma unroll
    for (int mt = 0; mt < 2; mt++)
#pragma unroll
        for (int nt = 0; nt < 9; nt++)
#pragma unroll
            for (int j = 0; j < 4; j++) acc[mt][nt][j] = 0.f;

    const int arow = warpM * 32 + (lane & 15);
    const int n0w = warpN * 72;
    const int csel = (lane >> 4) * 16;

    uint32_t ahf[2][2][4], alf[2][2][4], bhf[2][9][2];

    stage(0, 0);
    CP_WAIT0();
    __syncthreads();

    for (int s = 0; s < PRIM_NS; s++) {
        int cur = s & 1;
        if (s + 1 < PRIM_NS) stage(cur ^ 1, s + 1);

        uint32_t bA_h = sb + AH[cur], bA_l = sb + AL[cur], bB_h = sb + BH[cur];

#define LOADFRAG(PB, KS) do { \
        int kb_ = (KS) * 32; \
        uint32_t oa0_ = SWZ((uint32_t)(arow * 128 + kb_ + csel)); \
        uint32_t oa1_ = SWZ((uint32_t)((arow + 16) * 128 + kb_ + csel)); \
        ldm_x4(ahf[PB][0][0], ahf[PB][0][1], ahf[PB][0][2], ahf[PB][0][3], bA_h + oa0_); \
        ldm_x4(ahf[PB][1][0], ahf[PB][1][1], ahf[PB][1][2], ahf[PB][1][3], bA_h + oa1_); \
        ldm_x4(alf[PB][0][0], alf[PB][0][1], alf[PB][0][2], alf[PB][0][3], bA_l + oa0_); \
        ldm_x4(alf[PB][1][0], alf[PB][1][1], alf[PB][1][2], alf[PB][1][3], bA_l + oa1_); \
        _Pragma("unroll") \
        for (int p_ = 0; p_ < 4; p_++) { \
            uint32_t ob_ = SWZ((uint32_t)((n0w + p_ * 16 + (lane & 15)) * 128 + kb_ + csel)); \
            ldm_x4(bhf[PB][2 * p_][0], bhf[PB][2 * p_ + 1][0], \
                   bhf[PB][2 * p_][1], bhf[PB][2 * p_ + 1][1], bB_h + ob_); \
        } \
        { uint32_t ob2_ = SWZ((uint32_t)((n0w + 64 + (lane & 7)) * 128 + kb_ + \
                                         ((lane >> 3) & 1) * 16)); \
          ldm_x2(bhf[PB][8][0], bhf[PB][8][1], bB_h + ob2_); } \
    } while (0)

        LOADFRAG(0, 0);
#pragma unroll
        for (int ks = 0; ks < 4; ks++) {
            if (ks == 0) LOADFRAG(1, 1);
            else if (ks == 1) LOADFRAG(0, 2);
            else if (ks == 2) LOADFRAG(1, 3);
            const int fb = ks & 1;
#pragma unroll
            for (int mt = 0; mt < 2; mt++)
#pragma unroll
                for (int nt = 0; nt < 9; nt++) {
                    mma_f16(acc[mt][nt], ahf[fb][mt], bhf[fb][nt]);
                    mma_f16(acc[mt][nt], alf[fb][mt], bhf[fb][nt]);
                }
        }
#undef LOADFRAG
        if (s + 1 < PRIM_NS) CP_WAIT0();
        __syncthreads();
    }

    // epilogue: /32 + bias, squash over 8 atoms (lanes xor 4,8,16), write x3
    int atom = lane >> 2;
#pragma unroll
    for (int mt = 0; mt < 2; mt++) {
        int cobase = co0 + warpM * 32 + mt * 16;
        float bv0 = pb[cobase + atom];
        float bv1 = pb[cobase + 8 + atom];
        int cap0 = (cobase >> 3);
#pragma unroll
        for (int nt = 0; nt < 9; nt++) {
            float pr0 = acc[mt][nt][0] * (1.f / 32.f) + bv0;
            float pr1 = acc[mt][nt][1] * (1.f / 32.f) + bv0;
            float pr2 = acc[mt][nt][2] * (1.f / 32.f) + bv1;
            float pr3 = acc[mt][nt][3] * (1.f / 32.f) + bv1;
            float s0 = pr0 * pr0, s1 = pr1 * pr1, s2 = pr2 * pr2, s3 = pr3 * pr3;
#pragma unroll
            for (int d = 4; d <= 16; d <<= 1) {
                s0 += __shfl_xor_sync(0xffffffffu, s0, d);
                s1 += __shfl_xor_sync(0xffffffffu, s1, d);
                s2 += __shfl_xor_sync(0xffffffffu, s2, d);
                s3 += __shfl_xor_sync(0xffffffffu, s3, d);
            }
            float c0 = (s0 / (1.f + s0)) * rsqrtf(s0 + 1e-9f);
            float c1 = (s1 / (1.f + s1)) * rsqrtf(s1 + 1e-9f);
            float c2 = (s2 / (1.f + s2)) * rsqrtf(s2 + 1e-9f);
            float c3 = (s3 / (1.f + s3)) * rsqrtf(s3 + 1e-9f);
            int ncol = n0w + nt * 8 + (lane & 3) * 2;
            int bb = b0 + ncol / 36, sp = ncol % 36;
            float* base = g_x3 + bb * 9216;
            base[(cap0 * 36 + sp) * 8 + atom] = pr0 * c0;
            base[(cap0 * 36 + sp + 1) * 8 + atom] = pr1 * c1;
            base[((cap0 + 1) * 36 + sp) * 8 + atom] = pr2 * c2;
            base[((cap0 + 1) * 36 + sp + 1) * 8 + atom] = pr3 * c3;
        }
    }
}

// ---------------- K3: votes [i][b][ot] fp16, block per i ---------------------------
__global__ __launch_bounds__(256) void k_votes(const float* __restrict__ dw) {
    int i = blockIdx.x, t = threadIdx.x;    // t = b
    __shared__ float ws[1280];
    __shared__ float stg[256 * 17];
    for (int e = t; e < 1280; e += 256) ws[e] = dw[i * 1280 + e];
    const float4* xp = (const float4*)(g_x3 + t * 9216 + i * 8);
    float4 a0 = xp[0], a1 = xp[1];
    float xv[8] = {a0.x, a0.y, a0.z, a0.w, a1.x, a1.y, a1.z, a1.w};
    unsigned long long xpk[8];
#pragma unroll
    for (int a = 0; a < 8; a++) xpk[a] = pk2(xv[a], xv[a]);
    __syncthreads();
    __half2* orow2 = (__half2*)(g_votes + (long)i * 40960);
    for (int c = 0; c < 160; c += 16) {
        unsigned long long acc[8];
#pragma unroll
        for (int g = 0; g < 8; g++) acc[g] = 0ull;
#pragma unroll
        for (int a = 0; a < 8; a++) {
            const float2* wp = (const float2*)(ws + a * 160 + c);
#pragma unroll
            for (int g = 0; g < 8; g++) {
                float2 wv = wp[g];
                fma2(acc[g], xpk[a], pk2(wv.x, wv.y));
            }
        }
#pragma unroll
        for (int g = 0; g < 8; g++) {
            float2 f = upk2(acc[g]);
            stg[t * 17 + 2 * g] = f.x;
            stg[t * 17 + 2 * g + 1] = f.y;
        }
        __syncthreads();
        for (int e = t; e < 2048; e += 256) {
            int b = e >> 3, j = e & 7;
            orow2[b * 80 + (c >> 1) + j] =
                __floats2half2_rn(stg[b * 17 + 2 * j], stg[b * 17 + 2 * j + 1]);
        }
        __syncthreads();
    }
}

// ---------------- K4: fused 3-iteration routing (fp16 votes) -----------------------
__global__ __launch_bounds__(512) void k_route(const float* __restrict__ db,
                                               float* __restrict__ out_digit) {
    int b = blockIdx.x, t = threadIdx.x;
    int w = t >> 5, l = t & 31;
    __shared__ float act[160], asum[160], pre[160];
    __shared__ float red[16 * 160];
    const __half* V = g_votes + b * 160;

    {
        float p0[5] = {0.f, 0.f, 0.f, 0.f, 0.f};
        for (int i = w; i < 1152; i += 16) {
            const __half* vp = V + (long)i * 40960;
#pragma unroll
            for (int k = 0; k < 5; k++) p0[k] += __half2float(vp[32 * k + l]);
        }
#pragma unroll
        for (int k = 0; k < 5; k++) red[w * 160 + 32 * k + l] = p0[k];
    }
    __syncthreads();
    if (t < 160) {
        float s = 0.f;
#pragma unroll
        for (int ww = 0; ww < 16; ww++) s += red[ww * 160 + t];
        pre[t] = 0.1f * s + db[t];
    }
    __syncthreads();
    if (t < 160) {
        int o = t >> 4;
        float n2 = 0.f;
#pragma unroll
        for (int k = 0; k < 16; k++) { float v = pre[o * 16 + k]; n2 = fmaf(v, v, n2); }
        float a = pre[t] * (n2 / (1.f + n2)) * rsqrtf(n2 + 1e-9f);
        act[t] = a; asum[t] = a;
    }
    __syncthreads();

    for (int pass = 1; pass <= 2; pass++) {
        float pacc[5] = {0.f, 0.f, 0.f, 0.f, 0.f};
        for (int i = w; i < 1152; i += 16) {
            const __half* vp = V + (long)i * 40960;
            float v[5], d[5];
#pragma unroll
            for (int k = 0; k < 5; k++) v[k] = __half2float(vp[32 * k + l]);
#pragma unroll
            for (int k = 0; k < 5; k++) {
                float s = v[k] * asum[32 * k + l];
                s += __shfl_xor_sync(0xffffffffu, s, 1);
                s += __shfl_xor_sync(0xffffffffu, s, 2);
                s += __shfl_xor_sync(0xffffffffu, s, 4);
                s += __shfl_xor_sync(0xffffffffu, s, 8);
                d[k] = s;
            }
            float dn[5];
#pragma unroll
            for (int k = 0; k < 5; k++) dn[k] = __shfl_xor_sync(0xffffffffu, d[k], 16);
            float m = -1e30f;
#pragma unroll
            for (int k = 0; k < 5; k++) m = fmaxf(m, fmaxf(d[k], dn[k]));
            float sum = 0.f, e[5];
#pragma unroll
            for (int k = 0; k < 5; k++) {
                e[k] = __expf(d[k] - m); sum += e[k];
                sum += __expf(dn[k] - m);
            }
            float inv = 1.f / sum;
#pragma unroll
            for (int k = 0; k < 5; k++) pacc[k] = fmaf(e[k] * inv, v[k], pacc[k]);
        }
#pragma unroll
        for (int k = 0; k < 5; k++) red[w * 160 + 32 * k + l] = pacc[k];
        __syncthreads();
        if (t < 160) {
            float s = 0.f;
#pragma unroll
            for (int ww = 0; ww < 16; ww++) s += red[ww * 160 + t];
            pre[t] = s + db[t];
        }
        __syncthreads();
        if (t < 160) {
            int o = t >> 4;
            float n2 = 0.f;
#pragma unroll
            for (int k = 0; k < 16; k++) { float v = pre[o * 16 + k]; n2 = fmaf(v, v, n2); }
            float a = pre[t] * (n2 / (1.f + n2)) * rsqrtf(n2 + 1e-9f);
            act[t] = a;
            if (pass == 1) asum[t] += a;
        }
        __syncthreads();
    }
    if (t < 160) out_digit[b * 160 + t] = act[t];
}

// ---------------- K5: reconstruction MLP -------------------------------------------
__global__ __launch_bounds__(512) void k_fc1(const float* __restrict__ w1,
                                             const float* __restrict__ b1,
                                             const float* __restrict__ y,
                                             const float* __restrict__ digit) {
    int b = blockIdx.x, t = threadIdx.x;
    __shared__ float m[160];
    if (t < 160) m[t] = digit[b * 160 + t] * y[b * 10 + (t >> 4)];
    __syncthreads();
    float acc = b1[t];
#pragma unroll 8
    for (int k = 0; k < 160; k++) acc = fmaf(m[k], w1[k * 512 + t], acc);
    g_r1[b * 512 + t] = fmaxf(acc, 0.f);
}

__global__ __launch_bounds__(1024) void k_fc2(const float* __restrict__ w2,
                                              const float* __restrict__ b2) {
    int b0 = blockIdx.x * 2, t = threadIdx.x;
    __shared__ float m[2][512];
    if (t < 512) m[0][t] = g_r1[b0 * 512 + t];
    else m[1][t - 512] = g_r1[(b0 + 1) * 512 + t - 512];
    __syncthreads();
    float a0 = b2[t], a1 = a0;
#pragma unroll 8
    for (int k = 0; k < 512; k++) {
        float wv = w2[k * 1024 + t];
        a0 = fmaf(m[0][k], wv, a0);
        a1 = fmaf(m[1][k], wv, a1);
    }
    g_r2[b0 * 1024 + t] = fmaxf(a0, 0.f);
    g_r2[(b0 + 1) * 1024 + t] = fmaxf(a1, 0.f);
}

__global__ __launch_bounds__(784) void k_fc3(const float* __restrict__ w3,
                                             const float* __restrict__ b3,
                                             float* __restrict__ recon) {
    int b0 = blockIdx.x * 2, t = threadIdx.x;
    __shared__ float m[2][1024];
    for (int e = t; e < 2048; e += 784) {
        int bb = e >> 10;
        m[bb][e & 1023] = g_r2[(b0 + bb) * 1024 + (e & 1023)];
    }
    __syncthreads();
    float a0 = b3[t], a1 = a0;
#pragma unroll 8
    for (int k = 0; k < 1024; k++) {
        float wv = w3[k * 784 + t];
        a0 = fmaf(m[0][k], wv, a0);
        a1 = fmaf(m[1][k], wv, a1);
    }
    recon[b0 * 784 + t] = 1.f / (1.f + __expf(-a0));
    recon[(b0 + 1) * 784 + t] = 1.f / (1.f + __expf(-a1));
}

// ---------------- launch ------------------------------------------------------------
extern "C" void kernel_launch(void* const* d_in, const int* in_sizes, int n_in,
                              void* d_out, int out_size) {
    const float* x   = (const float*)d_in[0];
    const float* y   = (const float*)d_in[1];
    const float* c1w = (const float*)d_in[2];
    const float* c1b = (const float*)d_in[3];
    const float* pw  = (const float*)d_in[4];
    const float* pb  = (const float*)d_in[5];
    const float* dw  = (const float*)d_in[6];
    const float* db  = (const float*)d_in[7];
    const float* w1  = (const float*)d_in[8];
    const float* b1  = (const float*)d_in[9];
    const float* w2  = (const float*)d_in[10];
    const float* b2  = (const float*)d_in[11];
    const float* w3  = (const float*)d_in[12];
    const float* b3  = (const float*)d_in[13];
    float* out = (float*)d_out;   // digit [0,40960), recon [40960,241664)

    cudaFuncSetAttribute(k_prim, cudaFuncAttributeMaxDynamicSharedMemorySize, 102400);
    cudaFuncSetAttribute(k_wsplit, cudaFuncAttributeMaxDynamicSharedMemorySize, 82944);

    k_wsplit<<<256, 256, 82944>>>(pw);
    k_conv1<<<dim3(8, 256), 400>>>(x, c1w, c1b);
    k_prim<<<dim3(2, 64), 256, 102400>>>(pb);
    k_votes<<<1152, 256>>>(dw);
    k_route<<<256, 512>>>(db, out);
    k_fc1<<<256, 512>>>(w1, b1, y, out);
    k_fc2<<<128, 1024>>>(w2, b2);
    k_fc3<<<128, 784>>>(w3, b3, out + 40960);
}

// round 13
// speedup vs baseline: 1.1272x; 1.0490x over previous
#include <cuda_runtime.h>
#include <cuda_fp16.h>
#include <math.h>
#include <stdint.h>

// ---------------- scratch (device globals) ---------------------------------------
__device__ __half g_hh[26214400];          // conv1 out fp16, [b][pos400][ci256]
__device__ __half g_whi[5308416];          // prim weights hi fp16, [tap81][co256][ci256]
__device__ __half g_wlo[5308416];          // prim weights lo fp16
__device__ float g_x3[256 * 1152 * 8];     // squashed primary caps [b][i][a]
__device__ __half g_votes[47185920];       // votes fp16 [i][b][ot]
__device__ float g_r1[256 * 512];
__device__ float g_r2[256 * 1024];

// ---------------- f32x2 helpers ---------------------------------------------------
__device__ __forceinline__ unsigned long long pk2(float lo, float hi) {
    unsigned long long r;
    asm("mov.b64 %0, {%1, %2};" : "=l"(r) : "f"(lo), "f"(hi));
    return r;
}
__device__ __forceinline__ void fma2(unsigned long long& d, unsigned long long a,
                                     unsigned long long b) {
    asm("fma.rn.f32x2 %0, %1, %2, %0;" : "+l"(d) : "l"(a), "l"(b));
}
__device__ __forceinline__ float2 upk2(unsigned long long v) {
    float2 f;
    asm("mov.b64 {%0, %1}, %2;" : "=f"(f.x), "=f"(f.y) : "l"(v));
    return f;
}

// ---------------- baseline-PTX helpers --------------------------------------------
__device__ __forceinline__ uint32_t smem_to_u32(const void* p) {
    uint32_t a;
    asm("{ .reg .u64 t; cvta.to.shared.u64 t, %1; cvt.u32.u64 %0, t; }" : "=r"(a) : "l"(p));
    return a;
}
__device__ __forceinline__ void cpa16(uint32_t s, const void* g) {
    asm volatile("cp.async.cg.shared.global [%0], [%1], 16;" :: "r"(s), "l"(g));
}
#define CP_COMMIT() asm volatile("cp.async.commit_group;" ::: "memory")
#define CP_WAIT0()  asm volatile("cp.async.wait_group 0;" ::: "memory")

__device__ __forceinline__ void ldm_x4(uint32_t& r0, uint32_t& r1, uint32_t& r2,
                                       uint32_t& r3, uint32_t a) {
    asm volatile("ldmatrix.sync.aligned.m8n8.x4.shared.b16 {%0,%1,%2,%3}, [%4];"
                 : "=r"(r0), "=r"(r1), "=r"(r2), "=r"(r3) : "r"(a));
}
__device__ __forceinline__ void ldm_x2(uint32_t& r0, uint32_t& r1, uint32_t a) {
    asm volatile("ldmatrix.sync.aligned.m8n8.x2.shared.b16 {%0,%1}, [%2];"
                 : "=r"(r0), "=r"(r1) : "r"(a));
}
__device__ __forceinline__ void mma_f16(float* c, const uint32_t* a, const uint32_t* b) {
    asm volatile("mma.sync.aligned.m16n8k16.row.col.f32.f16.f16.f32 "
                 "{%0,%1,%2,%3}, {%4,%5,%6,%7}, {%8,%9}, {%0,%1,%2,%3};"
                 : "+f"(c[0]), "+f"(c[1]), "+f"(c[2]), "+f"(c[3])
                 : "r"(a[0]), "r"(a[1]), "r"(a[2]), "r"(a[3]), "r"(b[0]), "r"(b[1]));
}
#define SWZ(x) ((x) ^ (((x) >> 3) & 0x70))

// ---------------- P0: weight split/transpose, coalesced ---------------------------
__global__ __launch_bounds__(256) void k_wsplit(const float* __restrict__ pw) {
    extern __shared__ unsigned sbuf[];   // 81*256
    int co = blockIdx.x, ci = threadIdx.x;
    const float* src = pw + co * 20736 + ci * 81;
#pragma unroll
    for (int tap = 0; tap < 81; tap++) {
        float w = src[tap];
        __half h = __float2half(w);
        __half l = __float2half(w - __half2float(h));
        sbuf[tap * 256 + ci] = (unsigned)__half_as_ushort(h) |
                               ((unsigned)__half_as_ushort(l) << 16);
    }
    __syncthreads();
    for (int e = ci; e < 81 * 256; e += 256) {
        int tap = e >> 8, c2 = e & 255;
        unsigned v = sbuf[e];
        g_whi[tap * 65536 + co * 256 + c2] = __ushort_as_half((unsigned short)(v & 0xffff));
        g_wlo[tap * 65536 + co * 256 + c2] = __ushort_as_half((unsigned short)(v >> 16));
    }
}

// ---------------- K1: conv1 9x9 s1 + bias + relu -> fp16 [b][pos][ci] -------------
__global__ __launch_bounds__(400) void k_conv1(const float* __restrict__ x,
                                               const float* __restrict__ w,
                                               const float* __restrict__ bias) {
    int b = blockIdx.y, c0 = blockIdx.x * 32;
    __shared__ float img[784];
    __shared__ float ws[32 * 81];
    __shared__ float bs[32];
    __shared__ unsigned short spk[100 * 32];
    int t = threadIdx.x;
    for (int e = t; e < 784; e += 400) img[e] = x[b * 784 + e];
    for (int e = t; e < 2592; e += 400) ws[e] = w[c0 * 81 + e];
    if (t < 32) bs[t] = bias[c0 + t];
    __syncthreads();

    int pg = t % 100, chg = t / 100;
    int p0 = pg * 4;
    int oy = p0 / 20, ox0 = p0 % 20;

    unsigned long long acc2[4][4];
#pragma unroll
    for (int p = 0; p < 4; p++)
#pragma unroll
        for (int j = 0; j < 4; j++) acc2[p][j] = 0ull;

    for (int kh = 0; kh < 9; kh++) {
        const float* row = img + (oy + kh) * 28 + ox0;
        float xw[12];
#pragma unroll
        for (int i = 0; i < 12; i++) xw[i] = row[i];
#pragma unroll
        for (int kw = 0; kw < 9; kw++) {
            unsigned long long xp[4];
#pragma unroll
            for (int j = 0; j < 4; j++) xp[j] = pk2(xw[kw + j], xw[kw + j]);
#pragma unroll
            for (int p = 0; p < 4; p++) {
                unsigned long long wp = pk2(ws[(chg * 8 + 2 * p) * 81 + kh * 9 + kw],
                                            ws[(chg * 8 + 2 * p + 1) * 81 + kh * 9 + kw]);
#pragma unroll
                for (int j = 0; j < 4; j++) fma2(acc2[p][j], xp[j], wp);
            }
        }
    }

    unsigned short pkv[8][4];
#pragma unroll
    for (int p = 0; p < 4; p++) {
        float b0v = bs[chg * 8 + 2 * p], b1v = bs[chg * 8 + 2 * p + 1];
#pragma unroll
        for (int j = 0; j < 4; j++) {
            float2 f = upk2(acc2[p][j]);
            pkv[2 * p][j] = __half_as_ushort(__float2half(fmaxf(f.x + b0v, 0.f)));
            pkv[2 * p + 1][j] = __half_as_ushort(__float2half(fmaxf(f.y + b1v, 0.f)));
        }
    }
    for (int c = 0; c < 4; c++) {
        if (pg >= c * 25 && pg < c * 25 + 25) {
            int pl = p0 - c * 100;
#pragma unroll
            for (int ch = 0; ch < 8; ch++)
#pragma unroll
                for (int j = 0; j < 4; j++)
                    spk[(pl + j) * 32 + chg * 8 + ch] = pkv[ch][j];
        }
        __syncthreads();
        for (int e = t; e < 3200; e += 400) {
            int pl = e >> 5, ch = e & 31;
            g_hh[(b * 400 + c * 100 + pl) * 256 + c0 + ch] = __ushort_as_half(spk[e]);
        }
        __syncthreads();
    }
}

// ---------------- K2: primary-caps conv, fp16 2-term split, K=128/stage ------------
// grid (2 co-halves of 128, 64 b-groups of 4), 256 thr = 8 warps (4M x 2N).
// 162 stages of (tap, cb-pair); each stage = two 64-ci sub-tiles in their own
// 128B-row SW128 regions (conflict-free ldmatrix). 2 buffers x 100KB = 200KB smem.
static constexpr int PRIM_NS2 = 162;

__global__ __launch_bounds__(256, 1) void k_prim(const float* __restrict__ pb) {
    extern __shared__ char sm[];
    uint32_t sb = smem_to_u32(sm);
    const int t = threadIdx.x, wid = t >> 5, lane = t & 31;
    const int co0 = blockIdx.x * 128;
    const int b0 = blockIdx.y * 4;
    const int warpM = wid >> 1, warpN = wid & 1;

    // buffer layout (base + ...): AH0 0, AH1 16384, AL0 32768, AL1 49152,
    //                             BH0 65536, BH1 83968; buffer stride 102400.
    const uint32_t BUF[2] = {0u, 102400u};

    uint32_t a_sm[4]; long a_g[4];
#pragma unroll
    for (int k = 0; k < 4; k++) {
        int e = t + k * 256, row = e >> 3, q = e & 7;
        a_sm[k] = SWZ((uint32_t)(row * 128 + q * 16));
        a_g[k] = (long)(co0 + row) * 256 + q * 8;
    }
    uint32_t b_sm[5]; long b_g[5]; bool b_p[5];
#pragma unroll
    for (int k = 0; k < 5; k++) {
        int e = t + k * 256;
        b_p[k] = (e < 1152);
        int n = e >> 3, q = e & 7;
        if (!b_p[k]) { n = 0; q = 0; }
        int bb = n / 36, sp = n % 36, oy = sp / 6, ox = sp % 6;
        b_sm[k] = SWZ((uint32_t)(n * 128 + q * 16));
        b_g[k] = (long)((b0 + bb) * 400 + oy * 40 + ox * 2) * 256 + q * 8;
    }

    // stage s: tap = s>>1, cb pair = {2*(s&1), 2*(s&1)+1}
    auto stage = [&](int buf, int s) {
        int tap = s >> 1, cb0 = (s & 1) * 2;
        uint32_t base = sb + BUF[buf];
#pragma unroll
        for (int h = 0; h < 2; h++) {
            int cb = cb0 + h;
            long wofs = (long)tap * 65536 + cb * 64;
            long xofs = (long)((tap / 9) * 20 + (tap % 9)) * 256 + cb * 64;
            uint32_t ah = base + h * 16384u;
            uint32_t al = base + 32768u + h * 16384u;
            uint32_t bh = base + 65536u + h * 18432u;
#pragma unroll
            for (int k = 0; k < 4; k++) {
                cpa16(ah + a_sm[k], g_whi + wofs + a_g[k]);
                cpa16(al + a_sm[k], g_wlo + wofs + a_g[k]);
            }
#pragma unroll
            for (int k = 0; k < 5; k++)
                if (b_p[k]) cpa16(bh + b_sm[k], g_hh + xofs + b_g[k]);
        }
        CP_COMMIT();
    };

    float acc[2][9][4];
#pragma unroll
    for (int mt = 0; mt < 2; mt++)
#pragma unroll
        for (int nt = 0; nt < 9; nt++)
#pragma unroll
            for (int j = 0; j < 4; j++) acc[mt][nt][j] = 0.f;

    const int arow = warpM * 32 + (lane & 15);
    const int n0w = warpN * 72;
    const int csel = (lane >> 4) * 16;

    uint32_t ahf[2][2][4], alf[2][2][4], bhf[2][9][2];

    stage(0, 0);
    CP_WAIT0();
    __syncthreads();

    for (int s = 0; s < PRIM_NS2; s++) {
        int cur = s & 1;
        if (s + 1 < PRIM_NS2) stage(cur ^ 1, s + 1);

        uint32_t base = sb + BUF[cur];

#define LOADFRAG(PB, KS, AHB, ALB, BHB) do { \
        int kb_ = (KS) * 32; \
        uint32_t oa0_ = SWZ((uint32_t)(arow * 128 + kb_ + csel)); \
        uint32_t oa1_ = SWZ((uint32_t)((arow + 16) * 128 + kb_ + csel)); \
        ldm_x4(ahf[PB][0][0], ahf[PB][0][1], ahf[PB][0][2], ahf[PB][0][3], (AHB) + oa0_); \
        ldm_x4(ahf[PB][1][0], ahf[PB][1][1], ahf[PB][1][2], ahf[PB][1][3], (AHB) + oa1_); \
        ldm_x4(alf[PB][0][0], alf[PB][0][1], alf[PB][0][2], alf[PB][0][3], (ALB) + oa0_); \
        ldm_x4(alf[PB][1][0], alf[PB][1][1], alf[PB][1][2], alf[PB][1][3], (ALB) + oa1_); \
        _Pragma("unroll") \
        for (int p_ = 0; p_ < 4; p_++) { \
            uint32_t ob_ = SWZ((uint32_t)((n0w + p_ * 16 + (lane & 15)) * 128 + kb_ + csel)); \
            ldm_x4(bhf[PB][2 * p_][0], bhf[PB][2 * p_ + 1][0], \
                   bhf[PB][2 * p_][1], bhf[PB][2 * p_ + 1][1], (BHB) + ob_); \
        } \
        { uint32_t ob2_ = SWZ((uint32_t)((n0w + 64 + (lane & 7)) * 128 + kb_ + \
                                         ((lane >> 3) & 1) * 16)); \
          ldm_x2(bhf[PB][8][0], bhf[PB][8][1], (BHB) + ob2_); } \
    } while (0)

#pragma unroll
        for (int h = 0; h < 2; h++) {
            uint32_t AHB = base + h * 16384u;
            uint32_t ALB = base + 32768u + h * 16384u;
            uint32_t BHB = base + 65536u + h * 18432u;
            LOADFRAG(0, 0, AHB, ALB, BHB);
#pragma unroll
            for (int ks = 0; ks < 4; ks++) {
                if (ks == 0) LOADFRAG(1, 1, AHB, ALB, BHB);
                else if (ks == 1) LOADFRAG(0, 2, AHB, ALB, BHB);
                else if (ks == 2) LOADFRAG(1, 3, AHB, ALB, BHB);
                const int fb = ks & 1;
#pragma unroll
                for (int mt = 0; mt < 2; mt++)
#pragma unroll
                    for (int nt = 0; nt < 9; nt++) {
                        mma_f16(acc[mt][nt], ahf[fb][mt], bhf[fb][nt]);
                        mma_f16(acc[mt][nt], alf[fb][mt], bhf[fb][nt]);
                    }
            }
        }
#undef LOADFRAG
        if (s + 1 < PRIM_NS2) { CP_WAIT0(); }
        __syncthreads();
    }

    // epilogue: /32 + bias, squash over 8 atoms (lanes xor 4,8,16), write x3
    int atom = lane >> 2;
#pragma unroll
    for (int mt = 0; mt < 2; mt++) {
        int cobase = co0 + warpM * 32 + mt * 16;
        float bv0 = pb[cobase + atom];
        float bv1 = pb[cobase + 8 + atom];
        int cap0 = (cobase >> 3);
#pragma unroll
        for (int nt = 0; nt < 9; nt++) {
            float pr0 = acc[mt][nt][0] * (1.f / 32.f) + bv0;
            float pr1 = acc[mt][nt][1] * (1.f / 32.f) + bv0;
            float pr2 = acc[mt][nt][2] * (1.f / 32.f) + bv1;
            float pr3 = acc[mt][nt][3] * (1.f / 32.f) + bv1;
            float s0 = pr0 * pr0, s1 = pr1 * pr1, s2 = pr2 * pr2, s3 = pr3 * pr3;
#pragma unroll
            for (int d = 4; d <= 16; d <<= 1) {
                s0 += __shfl_xor_sync(0xffffffffu, s0, d);
                s1 += __shfl_xor_sync(0xffffffffu, s1, d);
                s2 += __shfl_xor_sync(0xffffffffu, s2, d);
                s3 += __shfl_xor_sync(0xffffffffu, s3, d);
            }
            float c0 = (s0 / (1.f + s0)) * rsqrtf(s0 + 1e-9f);
            float c1 = (s1 / (1.f + s1)) * rsqrtf(s1 + 1e-9f);
            float c2 = (s2 / (1.f + s2)) * rsqrtf(s2 + 1e-9f);
            float c3 = (s3 / (1.f + s3)) * rsqrtf(s3 + 1e-9f);
            int ncol = n0w + nt * 8 + (lane & 3) * 2;
            int bb = b0 + ncol / 36, sp = ncol % 36;
            float* base2 = g_x3 + bb * 9216;
            base2[(cap0 * 36 + sp) * 8 + atom] = pr0 * c0;
            base2[(cap0 * 36 + sp + 1) * 8 + atom] = pr1 * c1;
            base2[((cap0 + 1) * 36 + sp) * 8 + atom] = pr2 * c2;
            base2[((cap0 + 1) * 36 + sp + 1) * 8 + atom] = pr3 * c3;
        }
    }
}

// ---------------- K3: votes [i][b][ot] fp16, block per i ---------------------------
__global__ __launch_bounds__(256) void k_votes(const float* __restrict__ dw) {
    int i = blockIdx.x, t = threadIdx.x;    // t = b
    __shared__ float ws[1280];
    __shared__ float stg[256 * 17];
    for (int e = t; e < 1280; e += 256) ws[e] = dw[i * 1280 + e];
    const float4* xp = (const float4*)(g_x3 + t * 9216 + i * 8);
    float4 a0 = xp[0], a1 = xp[1];
    float xv[8] = {a0.x, a0.y, a0.z, a0.w, a1.x, a1.y, a1.z, a1.w};
    unsigned long long xpk[8];
#pragma unroll
    for (int a = 0; a < 8; a++) xpk[a] = pk2(xv[a], xv[a]);
    __syncthreads();
    __half2* orow2 = (__half2*)(g_votes + (long)i * 40960);
    for (int c = 0; c < 160; c += 16) {
        unsigned long long acc[8];
#pragma unroll
        for (int g = 0; g < 8; g++) acc[g] = 0ull;
#pragma unroll
        for (int a = 0; a < 8; a++) {
            const float2* wp = (const float2*)(ws + a * 160 + c);
#pragma unroll
            for (int g = 0; g < 8; g++) {
                float2 wv = wp[g];
                fma2(acc[g], xpk[a], pk2(wv.x, wv.y));
            }
        }
#pragma unroll
        for (int g = 0; g < 8; g++) {
            float2 f = upk2(acc[g]);
            stg[t * 17 + 2 * g] = f.x;
            stg[t * 17 + 2 * g + 1] = f.y;
        }
        __syncthreads();
        for (int e = t; e < 2048; e += 256) {
            int b = e >> 3, j = e & 7;
            orow2[b * 80 + (c >> 1) + j] =
                __floats2half2_rn(stg[b * 17 + 2 * j], stg[b * 17 + 2 * j + 1]);
        }
        __syncthreads();
    }
}

// ---------------- K4: fused 3-iteration routing (fp16 votes) -----------------------
__global__ __launch_bounds__(512) void k_route(const float* __restrict__ db,
                                               float* __restrict__ out_digit) {
    int b = blockIdx.x, t = threadIdx.x;
    int w = t >> 5, l = t & 31;
    __shared__ float act[160], asum[160], pre[160];
    __shared__ float red[16 * 160];
    const __half* V = g_votes + b * 160;

    {
        float p0[5] = {0.f, 0.f, 0.f, 0.f, 0.f};
        for (int i = w; i < 1152; i += 16) {
            const __half* vp = V + (long)i * 40960;
#pragma unroll
            for (int k = 0; k < 5; k++) p0[k] += __half2float(vp[32 * k + l]);
        }
#pragma unroll
        for (int k = 0; k < 5; k++) red[w * 160 + 32 * k + l] = p0[k];
    }
    __syncthreads();
    if (t < 160) {
        float s = 0.f;
#pragma unroll
        for (int ww = 0; ww < 16; ww++) s += red[ww * 160 + t];
        pre[t] = 0.1f * s + db[t];
    }
    __syncthreads();
    if (t < 160) {
        int o = t >> 4;
        float n2 = 0.f;
#pragma unroll
        for (int k = 0; k < 16; k++) { float v = pre[o * 16 + k]; n2 = fmaf(v, v, n2); }
        float a = pre[t] * (n2 / (1.f + n2)) * rsqrtf(n2 + 1e-9f);
        act[t] = a; asum[t] = a;
    }
    __syncthreads();

    for (int pass = 1; pass <= 2; pass++) {
        float pacc[5] = {0.f, 0.f, 0.f, 0.f, 0.f};
        for (int i = w; i < 1152; i += 16) {
            const __half* vp = V + (long)i * 40960;
            float v[5], d[5];
#pragma unroll
            for (int k = 0; k < 5; k++) v[k] = __half2float(vp[32 * k + l]);
#pragma unroll
            for (int k = 0; k < 5; k++) {
                float s = v[k] * asum[32 * k + l];
                s += __shfl_xor_sync(0xffffffffu, s, 1);
                s += __shfl_xor_sync(0xffffffffu, s, 2);
                s += __shfl_xor_sync(0xffffffffu, s, 4);
                s += __shfl_xor_sync(0xffffffffu, s, 8);
                d[k] = s;
            }
            float dn[5];
#pragma unroll
            for (int k = 0; k < 5; k++) dn[k] = __shfl_xor_sync(0xffffffffu, d[k], 16);
            float m = -1e30f;
#pragma unroll
            for (int k = 0; k < 5; k++) m = fmaxf(m, fmaxf(d[k], dn[k]));
            float sum = 0.f, e[5];
#pragma unroll
            for (int k = 0; k < 5; k++) {
                e[k] = __expf(d[k] - m); sum += e[k];
                sum += __expf(dn[k] - m);
            }
            float inv = 1.f / sum;
#pragma unroll
            for (int k = 0; k < 5; k++) pacc[k] = fmaf(e[k] * inv, v[k], pacc[k]);
        }
#pragma unroll
        for (int k = 0; k < 5; k++) red[w * 160 + 32 * k + l] = pacc[k];
        __syncthreads();
        if (t < 160) {
            float s = 0.f;
#pragma unroll
            for (int ww = 0; ww < 16; ww++) s += red[ww * 160 + t];
            pre[t] = s + db[t];
        }
        __syncthreads();
        if (t < 160) {
            int o = t >> 4;
            float n2 = 0.f;
#pragma unroll
            for (int k = 0; k < 16; k++) { float v = pre[o * 16 + k]; n2 = fmaf(v, v, n2); }
            float a = pre[t] * (n2 / (1.f + n2)) * rsqrtf(n2 + 1e-9f);
            act[t] = a;
            if (pass == 1) asum[t] += a;
        }
        __syncthreads();
    }
    if (t < 160) out_digit[b * 160 + t] = act[t];
}

// ---------------- K5: reconstruction MLP -------------------------------------------
__global__ __launch_bounds__(512) void k_fc1(const float* __restrict__ w1,
                                             const float* __restrict__ b1,
                                             const float* __restrict__ y,
                                             const float* __restrict__ digit) {
    int b0 = blockIdx.x * 2, t = threadIdx.x;
    __shared__ float m[2][160];
    if (t < 160) m[0][t] = digit[b0 * 160 + t] * y[b0 * 10 + (t >> 4)];
    else if (t >= 256 && t < 416) {
        int tt = t - 256;
        m[1][tt] = digit[(b0 + 1) * 160 + tt] * y[(b0 + 1) * 10 + (tt >> 4)];
    }
    __syncthreads();
    float a0 = b1[t], a1 = a0;
#pragma unroll 8
    for (int k = 0; k < 160; k++) {
        float wv = w1[k * 512 + t];
        a0 = fmaf(m[0][k], wv, a0);
        a1 = fmaf(m[1][k], wv, a1);
    }
    g_r1[b0 * 512 + t] = fmaxf(a0, 0.f);
    g_r1[(b0 + 1) * 512 + t] = fmaxf(a1, 0.f);
}

__global__ __launch_bounds__(1024) void k_fc2(const float* __restrict__ w2,
                                              const float* __restrict__ b2) {
    int b0 = blockIdx.x * 2, t = threadIdx.x;
    __shared__ float m[2][512];
    if (t < 512) m[0][t] = g_r1[b0 * 512 + t];
    else m[1][t - 512] = g_r1[(b0 + 1) * 512 + t - 512];
    __syncthreads();
    float a0 = b2[t], a1 = a0;
#pragma unroll 8
    for (int k = 0; k < 512; k++) {
        float wv = w2[k * 1024 + t];
        a0 = fmaf(m[0][k], wv, a0);
        a1 = fmaf(m[1][k], wv, a1);
    }
    g_r2[b0 * 1024 + t] = fmaxf(a0, 0.f);
    g_r2[(b0 + 1) * 1024 + t] = fmaxf(a1, 0.f);
}

__global__ __launch_bounds__(784) void k_fc3(const float* __restrict__ w3,
                                             const float* __restrict__ b3,
                                             float* __restrict__ recon) {
    int b0 = blockIdx.x * 2, t = threadIdx.x;
    __shared__ float m[2][1024];
    for (int e = t; e < 2048; e += 784) {
        int bb = e >> 10;
        m[bb][e & 1023] = g_r2[(b0 + bb) * 1024 + (e & 1023)];
    }
    __syncthreads();
    float a0 = b3[t], a1 = a0;
#pragma unroll 8
    for (int k = 0; k < 1024; k++) {
        float wv = w3[k * 784 + t];
        a0 = fmaf(m[0][k], wv, a0);
        a1 = fmaf(m[1][k], wv, a1);
    }
    recon[b0 * 784 + t] = 1.f / (1.f + __expf(-a0));
    recon[(b0 + 1) * 784 + t] = 1.f / (1.f + __expf(-a1));
}

// ---------------- launch ------------------------------------------------------------
extern "C" void kernel_launch(void* const* d_in, const int* in_sizes, int n_in,
                              void* d_out, int out_size) {
    const float* x   = (const float*)d_in[0];
    const float* y   = (const float*)d_in[1];
    const float* c1w = (const float*)d_in[2];
    const float* c1b = (const float*)d_in[3];
    const float* pw  = (const float*)d_in[4];
    const float* pb  = (const float*)d_in[5];
    const float* dw  = (const float*)d_in[6];
    const float* db  = (const float*)d_in[7];
    const float* w1  = (const float*)d_in[8];
    const float* b1  = (const float*)d_in[9];
    const float* w2  = (const float*)d_in[10];
    const float* b2  = (const float*)d_in[11];
    const float* w3  = (const float*)d_in[12];
    const float* b3  = (const float*)d_in[13];
    float* out = (float*)d_out;   // digit [0,40960), recon [40960,241664)

    cudaFuncSetAttribute(k_prim, cudaFuncAttributeMaxDynamicSharedMemorySize, 204800);
    cudaFuncSetAttribute(k_wsplit, cudaFuncAttributeMaxDynamicSharedMemorySize, 82944);

    k_wsplit<<<256, 256, 82944>>>(pw);
    k_conv1<<<dim3(8, 256), 400>>>(x, c1w, c1b);
    k_prim<<<dim3(2, 64), 256, 204800>>>(pb);
    k_votes<<<1152, 256>>>(dw);
    k_route<<<256, 512>>>(db, out);
    k_fc1<<<128, 512>>>(w1, b1, y, out);
    k_fc2<<<128, 1024>>>(w2, b2);
    k_fc3<<<128, 784>>>(w3, b3, out + 40960);
}

// round 14
// speedup vs baseline: 1.3745x; 1.2193x over previous
#include <cuda_runtime.h>
#include <cuda_fp16.h>
#include <math.h>
#include <stdint.h>

// ---------------- scratch (device globals) ---------------------------------------
__device__ __half g_hh[26214400];          // conv1 out fp16, [b][pos400][ci256]
__device__ __half g_whi[5308416];          // prim weights fp16, [tap81][co256][ci256]
__device__ float g_x3[256 * 1152 * 8];     // squashed primary caps [b][i][a]
__device__ __half g_votes[47185920];       // votes fp16 [i][b][ot]
__device__ float g_r1[256 * 512];
__device__ float g_r2[256 * 1024];

// ---------------- f32x2 helpers ---------------------------------------------------
__device__ __forceinline__ unsigned long long pk2(float lo, float hi) {
    unsigned long long r;
    asm("mov.b64 %0, {%1, %2};" : "=l"(r) : "f"(lo), "f"(hi));
    return r;
}
__device__ __forceinline__ void fma2(unsigned long long& d, unsigned long long a,
                                     unsigned long long b) {
    asm("fma.rn.f32x2 %0, %1, %2, %0;" : "+l"(d) : "l"(a), "l"(b));
}
__device__ __forceinline__ float2 upk2(unsigned long long v) {
    float2 f;
    asm("mov.b64 {%0, %1}, %2;" : "=f"(f.x), "=f"(f.y) : "l"(v));
    return f;
}

// ---------------- baseline-PTX helpers --------------------------------------------
__device__ __forceinline__ uint32_t smem_to_u32(const void* p) {
    uint32_t a;
    asm("{ .reg .u64 t; cvta.to.shared.u64 t, %1; cvt.u32.u64 %0, t; }" : "=r"(a) : "l"(p));
    return a;
}
__device__ __forceinline__ void cpa16(uint32_t s, const void* g) {
    asm volatile("cp.async.cg.shared.global [%0], [%1], 16;" :: "r"(s), "l"(g));
}
#define CP_COMMIT() asm volatile("cp.async.commit_group;" ::: "memory")
#define CP_WAIT0()  asm volatile("cp.async.wait_group 0;" ::: "memory")

__device__ __forceinline__ void ldm_x4(uint32_t& r0, uint32_t& r1, uint32_t& r2,
                                       uint32_t& r3, uint32_t a) {
    asm volatile("ldmatrix.sync.aligned.m8n8.x4.shared.b16 {%0,%1,%2,%3}, [%4];"
                 : "=r"(r0), "=r"(r1), "=r"(r2), "=r"(r3) : "r"(a));
}
__device__ __forceinline__ void ldm_x2(uint32_t& r0, uint32_t& r1, uint32_t a) {
    asm volatile("ldmatrix.sync.aligned.m8n8.x2.shared.b16 {%0,%1}, [%2];"
                 : "=r"(r0), "=r"(r1) : "r"(a));
}
__device__ __forceinline__ void mma_f16(float* c, const uint32_t* a, const uint32_t* b) {
    asm volatile("mma.sync.aligned.m16n8k16.row.col.f32.f16.f16.f32 "
                 "{%0,%1,%2,%3}, {%4,%5,%6,%7}, {%8,%9}, {%0,%1,%2,%3};"
                 : "+f"(c[0]), "+f"(c[1]), "+f"(c[2]), "+f"(c[3])
                 : "r"(a[0]), "r"(a[1]), "r"(a[2]), "r"(a[3]), "r"(b[0]), "r"(b[1]));
}
#define SWZ(x) ((x) ^ (((x) >> 3) & 0x70))

// ---------------- P0: weight fp16 transpose, coalesced -----------------------------
__global__ __launch_bounds__(256) void k_wsplit(const float* __restrict__ pw) {
    extern __shared__ unsigned short sbuf[];   // 81*256
    int co = blockIdx.x, ci = threadIdx.x;
    const float* src = pw + co * 20736 + ci * 81;
#pragma unroll
    for (int tap = 0; tap < 81; tap++)
        sbuf[tap * 256 + ci] = __half_as_ushort(__float2half(src[tap]));
    __syncthreads();
    for (int e = ci; e < 81 * 256; e += 256) {
        int tap = e >> 8, c2 = e & 255;
        g_whi[tap * 65536 + co * 256 + c2] = __ushort_as_half(sbuf[e]);
    }
}

// ---------------- K1: conv1 9x9 s1 + bias + relu -> fp16 [b][pos][ci] -------------
__global__ __launch_bounds__(400) void k_conv1(const float* __restrict__ x,
                                               const float* __restrict__ w,
                                               const float* __restrict__ bias) {
    int b = blockIdx.y, c0 = blockIdx.x * 32;
    __shared__ float img[784];
    __shared__ float ws[32 * 81];
    __shared__ float bs[32];
    __shared__ unsigned short spk[100 * 32];
    int t = threadIdx.x;
    for (int e = t; e < 784; e += 400) img[e] = x[b * 784 + e];
    for (int e = t; e < 2592; e += 400) ws[e] = w[c0 * 81 + e];
    if (t < 32) bs[t] = bias[c0 + t];
    __syncthreads();

    int pg = t % 100, chg = t / 100;
    int p0 = pg * 4;
    int oy = p0 / 20, ox0 = p0 % 20;

    unsigned long long acc2[4][4];
#pragma unroll
    for (int p = 0; p < 4; p++)
#pragma unroll
        for (int j = 0; j < 4; j++) acc2[p][j] = 0ull;

    for (int kh = 0; kh < 9; kh++) {
        const float* row = img + (oy + kh) * 28 + ox0;
        float xw[12];
#pragma unroll
        for (int i = 0; i < 12; i++) xw[i] = row[i];
#pragma unroll
        for (int kw = 0; kw < 9; kw++) {
            unsigned long long xp[4];
#pragma unroll
            for (int j = 0; j < 4; j++) xp[j] = pk2(xw[kw + j], xw[kw + j]);
#pragma unroll
            for (int p = 0; p < 4; p++) {
                unsigned long long wp = pk2(ws[(chg * 8 + 2 * p) * 81 + kh * 9 + kw],
                                            ws[(chg * 8 + 2 * p + 1) * 81 + kh * 9 + kw]);
#pragma unroll
                for (int j = 0; j < 4; j++) fma2(acc2[p][j], xp[j], wp);
            }
        }
    }

    unsigned short pkv[8][4];
#pragma unroll
    for (int p = 0; p < 4; p++) {
        float b0v = bs[chg * 8 + 2 * p], b1v = bs[chg * 8 + 2 * p + 1];
#pragma unroll
        for (int j = 0; j < 4; j++) {
            float2 f = upk2(acc2[p][j]);
            pkv[2 * p][j] = __half_as_ushort(__float2half(fmaxf(f.x + b0v, 0.f)));
            pkv[2 * p + 1][j] = __half_as_ushort(__float2half(fmaxf(f.y + b1v, 0.f)));
        }
    }
    for (int c = 0; c < 4; c++) {
        if (pg >= c * 25 && pg < c * 25 + 25) {
            int pl = p0 - c * 100;
#pragma unroll
            for (int ch = 0; ch < 8; ch++)
#pragma unroll
                for (int j = 0; j < 4; j++)
                    spk[(pl + j) * 32 + chg * 8 + ch] = pkv[ch][j];
        }
        __syncthreads();
        for (int e = t; e < 3200; e += 400) {
            int pl = e >> 5, ch = e & 31;
            g_hh[(b * 400 + c * 100 + pl) * 256 + c0 + ch] = __ushort_as_half(spk[e]);
        }
        __syncthreads();
    }
}

// ---------------- K2: primary-caps conv, single-term fp16, K=128/stage -------------
// grid (2 co-halves of 128, 64 b-groups of 4), 256 thr = 8 warps (4M x 2N).
// 162 stages; buffer = AH0(16K) AH1(16K) BH0(18K) BH1(18K) = 68K x2 = 136K smem.
static constexpr int PRIM_NS2 = 162;

__global__ __launch_bounds__(256, 1) void k_prim(const float* __restrict__ pb) {
    extern __shared__ char sm[];
    uint32_t sb = smem_to_u32(sm);
    const int t = threadIdx.x, wid = t >> 5, lane = t & 31;
    const int co0 = blockIdx.x * 128;
    const int b0 = blockIdx.y * 4;
    const int warpM = wid >> 1, warpN = wid & 1;

    const uint32_t BUF[2] = {0u, 69632u};   // stride 68K->69632 (1K-aligned)

    uint32_t a_sm[4]; long a_g[4];
#pragma unroll
    for (int k = 0; k < 4; k++) {
        int e = t + k * 256, row = e >> 3, q = e & 7;
        a_sm[k] = SWZ((uint32_t)(row * 128 + q * 16));
        a_g[k] = (long)(co0 + row) * 256 + q * 8;
    }
    uint32_t b_sm[5]; long b_g[5]; bool b_p[5];
#pragma unroll
    for (int k = 0; k < 5; k++) {
        int e = t + k * 256;
        b_p[k] = (e < 1152);
        int n = e >> 3, q = e & 7;
        if (!b_p[k]) { n = 0; q = 0; }
        int bb = n / 36, sp = n % 36, oy = sp / 6, ox = sp % 6;
        b_sm[k] = SWZ((uint32_t)(n * 128 + q * 16));
        b_g[k] = (long)((b0 + bb) * 400 + oy * 40 + ox * 2) * 256 + q * 8;
    }

    // stage s: tap = s>>1, cb pair = {2*(s&1), 2*(s&1)+1}
    auto stage = [&](int buf, int s) {
        int tap = s >> 1, cb0 = (s & 1) * 2;
        uint32_t base = sb + BUF[buf];
#pragma unroll
        for (int h = 0; h < 2; h++) {
            int cb = cb0 + h;
            long wofs = (long)tap * 65536 + cb * 64;
            long xofs = (long)((tap / 9) * 20 + (tap % 9)) * 256 + cb * 64;
            uint32_t ah = base + h * 16384u;
            uint32_t bh = base + 32768u + h * 18432u;
#pragma unroll
            for (int k = 0; k < 4; k++)
                cpa16(ah + a_sm[k], g_whi + wofs + a_g[k]);
#pragma unroll
            for (int k = 0; k < 5; k++)
                if (b_p[k]) cpa16(bh + b_sm[k], g_hh + xofs + b_g[k]);
        }
        CP_COMMIT();
    };

    float acc[2][9][4];
#pragma unroll
    for (int mt = 0; mt < 2; mt++)
#pragma unroll
        for (int nt = 0; nt < 9; nt++)
#pragma unroll
            for (int j = 0; j < 4; j++) acc[mt][nt][j] = 0.f;

    const int arow = warpM * 32 + (lane & 15);
    const int n0w = warpN * 72;
    const int csel = (lane >> 4) * 16;

    uint32_t ahf[2][2][4], bhf[2][9][2];

    stage(0, 0);
    CP_WAIT0();
    __syncthreads();

    for (int s = 0; s < PRIM_NS2; s++) {
        int cur = s & 1;
        if (s + 1 < PRIM_NS2) stage(cur ^ 1, s + 1);

        uint32_t base = sb + BUF[cur];

#define LOADFRAG(PB, KS, AHB, BHB) do { \
        int kb_ = (KS) * 32; \
        uint32_t oa0_ = SWZ((uint32_t)(arow * 128 + kb_ + csel)); \
        uint32_t oa1_ = SWZ((uint32_t)((arow + 16) * 128 + kb_ + csel)); \
        ldm_x4(ahf[PB][0][0], ahf[PB][0][1], ahf[PB][0][2], ahf[PB][0][3], (AHB) + oa0_); \
        ldm_x4(ahf[PB][1][0], ahf[PB][1][1], ahf[PB][1][2], ahf[PB][1][3], (AHB) + oa1_); \
        _Pragma("unroll") \
        for (int p_ = 0; p_ < 4; p_++) { \
            uint32_t ob_ = SWZ((uint32_t)((n0w + p_ * 16 + (lane & 15)) * 128 + kb_ + csel)); \
            ldm_x4(bhf[PB][2 * p_][0], bhf[PB][2 * p_ + 1][0], \
                   bhf[PB][2 * p_][1], bhf[PB][2 * p_ + 1][1], (BHB) + ob_); \
        } \
        { uint32_t ob2_ = SWZ((uint32_t)((n0w + 64 + (lane & 7)) * 128 + kb_ + \
                                         ((lane >> 3) & 1) * 16)); \
          ldm_x2(bhf[PB][8][0], bhf[PB][8][1], (BHB) + ob2_); } \
    } while (0)

#pragma unroll
        for (int h = 0; h < 2; h++) {
            uint32_t AHB = base + h * 16384u;
            uint32_t BHB = base + 32768u + h * 18432u;
            LOADFRAG(0, 0, AHB, BHB);
#pragma unroll
            for (int ks = 0; ks < 4; ks++) {
                if (ks == 0) LOADFRAG(1, 1, AHB, BHB);
                else if (ks == 1) LOADFRAG(0, 2, AHB, BHB);
                else if (ks == 2) LOADFRAG(1, 3, AHB, BHB);
                const int fb = ks & 1;
#pragma unroll
                for (int mt = 0; mt < 2; mt++)
#pragma unroll
                    for (int nt = 0; nt < 9; nt++)
                        mma_f16(acc[mt][nt], ahf[fb][mt], bhf[fb][nt]);
            }
        }
#undef LOADFRAG
        if (s + 1 < PRIM_NS2) { CP_WAIT0(); }
        __syncthreads();
    }

    // epilogue: /32 + bias, squash over 8 atoms (lanes xor 4,8,16), write x3
    int atom = lane >> 2;
#pragma unroll
    for (int mt = 0; mt < 2; mt++) {
        int cobase = co0 + warpM * 32 + mt * 16;
        float bv0 = pb[cobase + atom];
        float bv1 = pb[cobase + 8 + atom];
        int cap0 = (cobase >> 3);
#pragma unroll
        for (int nt = 0; nt < 9; nt++) {
            float pr0 = acc[mt][nt][0] * (1.f / 32.f) + bv0;
            float pr1 = acc[mt][nt][1] * (1.f / 32.f) + bv0;
            float pr2 = acc[mt][nt][2] * (1.f / 32.f) + bv1;
            float pr3 = acc[mt][nt][3] * (1.f / 32.f) + bv1;
            float s0 = pr0 * pr0, s1 = pr1 * pr1, s2 = pr2 * pr2, s3 = pr3 * pr3;
#pragma unroll
            for (int d = 4; d <= 16; d <<= 1) {
                s0 += __shfl_xor_sync(0xffffffffu, s0, d);
                s1 += __shfl_xor_sync(0xffffffffu, s1, d);
                s2 += __shfl_xor_sync(0xffffffffu, s2, d);
                s3 += __shfl_xor_sync(0xffffffffu, s3, d);
            }
            float c0 = (s0 / (1.f + s0)) * rsqrtf(s0 + 1e-9f);
            float c1 = (s1 / (1.f + s1)) * rsqrtf(s1 + 1e-9f);
            float c2 = (s2 / (1.f + s2)) * rsqrtf(s2 + 1e-9f);
            float c3 = (s3 / (1.f + s3)) * rsqrtf(s3 + 1e-9f);
            int ncol = n0w + nt * 8 + (lane & 3) * 2;
            int bb = b0 + ncol / 36, sp = ncol % 36;
            float* base2 = g_x3 + bb * 9216;
            base2[(cap0 * 36 + sp) * 8 + atom] = pr0 * c0;
            base2[(cap0 * 36 + sp + 1) * 8 + atom] = pr1 * c1;
            base2[((cap0 + 1) * 36 + sp) * 8 + atom] = pr2 * c2;
            base2[((cap0 + 1) * 36 + sp + 1) * 8 + atom] = pr3 * c3;
        }
    }
}

// ---------------- K3: votes [i][b][ot] fp16, block per i ---------------------------
__global__ __launch_bounds__(256) void k_votes(const float* __restrict__ dw) {
    int i = blockIdx.x, t = threadIdx.x;    // t = b
    __shared__ float ws[1280];
    __shared__ float stg[256 * 17];
    for (int e = t; e < 1280; e += 256) ws[e] = dw[i * 1280 + e];
    const float4* xp = (const float4*)(g_x3 + t * 9216 + i * 8);
    float4 a0 = xp[0], a1 = xp[1];
    float xv[8] = {a0.x, a0.y, a0.z, a0.w, a1.x, a1.y, a1.z, a1.w};
    unsigned long long xpk[8];
#pragma unroll
    for (int a = 0; a < 8; a++) xpk[a] = pk2(xv[a], xv[a]);
    __syncthreads();
    __half2* orow2 = (__half2*)(g_votes + (long)i * 40960);
    for (int c = 0; c < 160; c += 16) {
        unsigned long long acc[8];
#pragma unroll
        for (int g = 0; g < 8; g++) acc[g] = 0ull;
#pragma unroll
        for (int a = 0; a < 8; a++) {
            const float2* wp = (const float2*)(ws + a * 160 + c);
#pragma unroll
            for (int g = 0; g < 8; g++) {
                float2 wv = wp[g];
                fma2(acc[g], xpk[a], pk2(wv.x, wv.y));
            }
        }
#pragma unroll
        for (int g = 0; g < 8; g++) {
            float2 f = upk2(acc[g]);
            stg[t * 17 + 2 * g] = f.x;
            stg[t * 17 + 2 * g + 1] = f.y;
        }
        __syncthreads();
        for (int e = t; e < 2048; e += 256) {
            int b = e >> 3, j = e & 7;
            orow2[b * 80 + (c >> 1) + j] =
                __floats2half2_rn(stg[b * 17 + 2 * j], stg[b * 17 + 2 * j + 1]);
        }
        __syncthreads();
    }
}

// ---------------- K4: fused 3-iteration routing (fp16 votes) -----------------------
__global__ __launch_bounds__(512) void k_route(const float* __restrict__ db,
                                               float* __restrict__ out_digit) {
    int b = blockIdx.x, t = threadIdx.x;
    int w = t >> 5, l = t & 31;
    __shared__ float act[160], asum[160], pre[160];
    __shared__ float red[16 * 160];
    const __half* V = g_votes + b * 160;

    {
        float p0[5] = {0.f, 0.f, 0.f, 0.f, 0.f};
        for (int i = w; i < 1152; i += 16) {
            const __half* vp = V + (long)i * 40960;
#pragma unroll
            for (int k = 0; k < 5; k++) p0[k] += __half2float(vp[32 * k + l]);
        }
#pragma unroll
        for (int k = 0; k < 5; k++) red[w * 160 + 32 * k + l] = p0[k];
    }
    __syncthreads();
    if (t < 160) {
        float s = 0.f;
#pragma unroll
        for (int ww = 0; ww < 16; ww++) s += red[ww * 160 + t];
        pre[t] = 0.1f * s + db[t];
    }
    __syncthreads();
    if (t < 160) {
        int o = t >> 4;
        float n2 = 0.f;
#pragma unroll
        for (int k = 0; k < 16; k++) { float v = pre[o * 16 + k]; n2 = fmaf(v, v, n2); }
        float a = pre[t] * (n2 / (1.f + n2)) * rsqrtf(n2 + 1e-9f);
        act[t] = a; asum[t] = a;
    }
    __syncthreads();

    for (int pass = 1; pass <= 2; pass++) {
        float pacc[5] = {0.f, 0.f, 0.f, 0.f, 0.f};
        for (int i = w; i < 1152; i += 16) {
            const __half* vp = V + (long)i * 40960;
            float v[5], d[5];
#pragma unroll
            for (int k = 0; k < 5; k++) v[k] = __half2float(vp[32 * k + l]);
#pragma unroll
            for (int k = 0; k < 5; k++) {
                float s = v[k] * asum[32 * k + l];
                s += __shfl_xor_sync(0xffffffffu, s, 1);
                s += __shfl_xor_sync(0xffffffffu, s, 2);
                s += __shfl_xor_sync(0xffffffffu, s, 4);
                s += __shfl_xor_sync(0xffffffffu, s, 8);
                d[k] = s;
            }
            float dn[5];
#pragma unroll
            for (int k = 0; k < 5; k++) dn[k] = __shfl_xor_sync(0xffffffffu, d[k], 16);
            float m = -1e30f;
#pragma unroll
            for (int k = 0; k < 5; k++) m = fmaxf(m, fmaxf(d[k], dn[k]));
            float sum = 0.f, e[5];
#pragma unroll
            for (int k = 0; k < 5; k++) {
                e[k] = __expf(d[k] - m); sum += e[k];
                sum += __expf(dn[k] - m);
            }
            float inv = 1.f / sum;
#pragma unroll
            for (int k = 0; k < 5; k++) pacc[k] = fmaf(e[k] * inv, v[k], pacc[k]);
        }
#pragma unroll
        for (int k = 0; k < 5; k++) red[w * 160 + 32 * k + l] = pacc[k];
        __syncthreads();
        if (t < 160) {
            float s = 0.f;
#pragma unroll
            for (int ww = 0; ww < 16; ww++) s += red[ww * 160 + t];
            pre[t] = s + db[t];
        }
        __syncthreads();
        if (t < 160) {
            int o = t >> 4;
            float n2 = 0.f;
#pragma unroll
            for (int k = 0; k < 16; k++) { float v = pre[o * 16 + k]; n2 = fmaf(v, v, n2); }
            float a = pre[t] * (n2 / (1.f + n2)) * rsqrtf(n2 + 1e-9f);
            act[t] = a;
            if (pass == 1) asum[t] += a;
        }
        __syncthreads();
    }
    if (t < 160) out_digit[b * 160 + t] = act[t];
}

// ---------------- K5: reconstruction MLP -------------------------------------------
__global__ __launch_bounds__(512) void k_fc1(const float* __restrict__ w1,
                                             const float* __restrict__ b1,
                                             const float* __restrict__ y,
                                             const float* __restrict__ digit) {
    int b0 = blockIdx.x * 2, t = threadIdx.x;
    __shared__ float m[2][160];
    if (t < 160) m[0][t] = digit[b0 * 160 + t] * y[b0 * 10 + (t >> 4)];
    else if (t >= 256 && t < 416) {
        int tt = t - 256;
        m[1][tt] = digit[(b0 + 1) * 160 + tt] * y[(b0 + 1) * 10 + (tt >> 4)];
    }
    __syncthreads();
    float a0 = b1[t], a1 = a0;
#pragma unroll 8
    for (int k = 0; k < 160; k++) {
        float wv = w1[k * 512 + t];
        a0 = fmaf(m[0][k], wv, a0);
        a1 = fmaf(m[1][k], wv, a1);
    }
    g_r1[b0 * 512 + t] = fmaxf(a0, 0.f);
    g_r1[(b0 + 1) * 512 + t] = fmaxf(a1, 0.f);
}

__global__ __launch_bounds__(1024) void k_fc2(const float* __restrict__ w2,
                                              const float* __restrict__ b2) {
    int b0 = blockIdx.x * 2, t = threadIdx.x;
    __shared__ float m[2][512];
    if (t < 512) m[0][t] = g_r1[b0 * 512 + t];
    else m[1][t - 512] = g_r1[(b0 + 1) * 512 + t - 512];
    __syncthreads();
    float a0 = b2[t], a1 = a0;
#pragma unroll 8
    for (int k = 0; k < 512; k++) {
        float wv = w2[k * 1024 + t];
        a0 = fmaf(m[0][k], wv, a0);
        a1 = fmaf(m[1][k], wv, a1);
    }
    g_r2[b0 * 1024 + t] = fmaxf(a0, 0.f);
    g_r2[(b0 + 1) * 1024 + t] = fmaxf(a1, 0.f);
}

__global__ __launch_bounds__(784) void k_fc3(const float* __restrict__ w3,
                                             const float* __restrict__ b3,
                                             float* __restrict__ recon) {
    int b0 = blockIdx.x * 2, t = threadIdx.x;
    __shared__ float m[2][1024];
    for (int e = t; e < 2048; e += 784) {
        int bb = e >> 10;
        m[bb][e & 1023] = g_r2[(b0 + bb) * 1024 + (e & 1023)];
    }
    __syncthreads();
    float a0 = b3[t], a1 = a0;
#pragma unroll 8
    for (int k = 0; k < 1024; k++) {
        float wv = w3[k * 784 + t];
        a0 = fmaf(m[0][k], wv, a0);
        a1 = fmaf(m[1][k], wv, a1);
    }
    recon[b0 * 784 + t] = 1.f / (1.f + __expf(-a0));
    recon[(b0 + 1) * 784 + t] = 1.f / (1.f + __expf(-a1));
}

// ---------------- launch ------------------------------------------------------------
extern "C" void kernel_launch(void* const* d_in, const int* in_sizes, int n_in,
                              void* d_out, int out_size) {
    const float* x   = (const float*)d_in[0];
    const float* y   = (const float*)d_in[1];
    const float* c1w = (const float*)d_in[2];
    const float* c1b = (const float*)d_in[3];
    const float* pw  = (const float*)d_in[4];
    const float* pb  = (const float*)d_in[5];
    const float* dw  = (const float*)d_in[6];
    const float* db  = (const float*)d_in[7];
    const float* w1  = (const float*)d_in[8];
    const float* b1  = (const float*)d_in[9];
    const float* w2  = (const float*)d_in[10];
    const float* b2  = (const float*)d_in[11];
    const float* w3  = (const float*)d_in[12];
    const float* b3  = (const float*)d_in[13];
    float* out = (float*)d_out;   // digit [0,40960), recon [40960,241664)

    cudaFuncSetAttribute(k_prim, cudaFuncAttributeMaxDynamicSharedMemorySize, 139264);
    cudaFuncSetAttribute(k_wsplit, cudaFuncAttributeMaxDynamicSharedMemorySize, 41472);

    k_wsplit<<<256, 256, 41472>>>(pw);
    k_conv1<<<dim3(8, 256), 400>>>(x, c1w, c1b);
    k_prim<<<dim3(2, 64), 256, 139264>>>(pb);
    k_votes<<<1152, 256>>>(dw);
    k_route<<<256, 512>>>(db, out);
    k_fc1<<<128, 512>>>(w1, b1, y, out);
    k_fc2<<<128, 1024>>>(w2, b2);
    k_fc3<<<128, 784>>>(w3, b3, out + 40960);
}

// round 16
// speedup vs baseline: 1.4235x; 1.0357x over previous
#include <cuda_runtime.h>
#include <cuda_fp16.h>
#include <math.h>
#include <stdint.h>

// ---------------- scratch (device globals) ---------------------------------------
__device__ __half g_hh[26214400];          // conv1 out fp16, [b][pos400][ci256]
__device__ __half g_whi[5308416];          // prim weights fp16, [tap81][co256][ci256]
__device__ float g_x3[256 * 1152 * 8];     // squashed primary caps [b][i][a]
__device__ __half g_votes[47185920];       // votes fp16 [i][b][ot]
__device__ float g_r1[256 * 512];
__device__ float g_r2[256 * 1024];

// ---------------- f32x2 helpers ---------------------------------------------------
__device__ __forceinline__ unsigned long long pk2(float lo, float hi) {
    unsigned long long r;
    asm("mov.b64 %0, {%1, %2};" : "=l"(r) : "f"(lo), "f"(hi));
    return r;
}
__device__ __forceinline__ void fma2(unsigned long long& d, unsigned long long a,
                                     unsigned long long b) {
    asm("fma.rn.f32x2 %0, %1, %2, %0;" : "+l"(d) : "l"(a), "l"(b));
}
__device__ __forceinline__ float2 upk2(unsigned long long v) {
    float2 f;
    asm("mov.b64 {%0, %1}, %2;" : "=f"(f.x), "=f"(f.y) : "l"(v));
    return f;
}

// ---------------- baseline-PTX helpers --------------------------------------------
__device__ __forceinline__ uint32_t smem_to_u32(const void* p) {
    uint32_t a;
    asm("{ .reg .u64 t; cvta.to.shared.u64 t, %1; cvt.u32.u64 %0, t; }" : "=r"(a) : "l"(p));
    return a;
}
__device__ __forceinline__ void cpa16(uint32_t s, const void* g) {
    asm volatile("cp.async.cg.shared.global [%0], [%1], 16;" :: "r"(s), "l"(g));
}
#define CP_COMMIT() asm volatile("cp.async.commit_group;" ::: "memory")
#define CP_WAIT0()  asm volatile("cp.async.wait_group 0;" ::: "memory")

__device__ __forceinline__ void ldm_x4(uint32_t& r0, uint32_t& r1, uint32_t& r2,
                                       uint32_t& r3, uint32_t a) {
    asm volatile("ldmatrix.sync.aligned.m8n8.x4.shared.b16 {%0,%1,%2,%3}, [%4];"
                 : "=r"(r0), "=r"(r1), "=r"(r2), "=r"(r3) : "r"(a));
}
__device__ __forceinline__ void ldm_x2(uint32_t& r0, uint32_t& r1, uint32_t a) {
    asm volatile("ldmatrix.sync.aligned.m8n8.x2.shared.b16 {%0,%1}, [%2];"
                 : "=r"(r0), "=r"(r1) : "r"(a));
}
__device__ __forceinline__ void mma_f16(float* c, const uint32_t* a, const uint32_t* b) {
    asm volatile("mma.sync.aligned.m16n8k16.row.col.f32.f16.f16.f32 "
                 "{%0,%1,%2,%3}, {%4,%5,%6,%7}, {%8,%9}, {%0,%1,%2,%3};"
                 : "+f"(c[0]), "+f"(c[1]), "+f"(c[2]), "+f"(c[3])
                 : "r"(a[0]), "r"(a[1]), "r"(a[2]), "r"(a[3]), "r"(b[0]), "r"(b[1]));
}
#define SWZ(x) ((x) ^ (((x) >> 3) & 0x70))

// ---------------- K1: fused (wsplit | conv1) ---------------------------------------
// blocks [0,256): weight fp16 transpose [co][ci][tap] -> [tap][co][ci]
// blocks [256,2304): conv1 9x9 s1 + bias + relu -> fp16 [b][pos][ci]
__global__ __launch_bounds__(400) void k_pre(const float* __restrict__ pw,
                                             const float* __restrict__ x,
                                             const float* __restrict__ w,
                                             const float* __restrict__ bias) {
    extern __shared__ char dsm[];
    int t = threadIdx.x;

    if (blockIdx.x < 256) {
        // ---- wsplit ----
        unsigned short* sbuf = (unsigned short*)dsm;   // 81*256 ushort = 41472 B
        int co = blockIdx.x;
        if (t < 256) {
            const float* src = pw + co * 20736 + t * 81;
#pragma unroll
            for (int tap = 0; tap < 81; tap++)
                sbuf[tap * 256 + t] = __half_as_ushort(__float2half(src[tap]));
        }
        __syncthreads();
        for (int e = t; e < 81 * 256; e += 400) {
            int tap = e >> 8, c2 = e & 255;
            g_whi[tap * 65536 + co * 256 + c2] = __ushort_as_half(sbuf[e]);
        }
        return;
    }

    // ---- conv1 ----
    int blk = blockIdx.x - 256;
    int b = blk >> 3, c0 = (blk & 7) * 32;
    float* img = (float*)dsm;                    // 784
    float* ws = img + 784;                       // 2592
    float* bs = ws + 2592;                       // 32
    unsigned short* spk = (unsigned short*)(bs + 32);   // 3200 ushort

    for (int e = t; e < 784; e += 400) img[e] = x[b * 784 + e];
    for (int e = t; e < 2592; e += 400) ws[e] = w[c0 * 81 + e];
    if (t < 32) bs[t] = bias[c0 + t];
    __syncthreads();

    int pg = t % 100, chg = t / 100;
    int p0 = pg * 4;
    int oy = p0 / 20, ox0 = p0 % 20;

    unsigned long long acc2[4][4];
#pragma unroll
    for (int p = 0; p < 4; p++)
#pragma unroll
        for (int j = 0; j < 4; j++) acc2[p][j] = 0ull;

    for (int kh = 0; kh < 9; kh++) {
        const float* row = img + (oy + kh) * 28 + ox0;
        float xw[12];
#pragma unroll
        for (int i = 0; i < 12; i++) xw[i] = row[i];
#pragma unroll
        for (int kw = 0; kw < 9; kw++) {
            unsigned long long xp[4];
#pragma unroll
            for (int j = 0; j < 4; j++) xp[j] = pk2(xw[kw + j], xw[kw + j]);
#pragma unroll
            for (int p = 0; p < 4; p++) {
                unsigned long long wp = pk2(ws[(chg * 8 + 2 * p) * 81 + kh * 9 + kw],
                                            ws[(chg * 8 + 2 * p + 1) * 81 + kh * 9 + kw]);
#pragma unroll
                for (int j = 0; j < 4; j++) fma2(acc2[p][j], xp[j], wp);
            }
        }
    }

    unsigned short pkv[8][4];
#pragma unroll
    for (int p = 0; p < 4; p++) {
        float b0v = bs[chg * 8 + 2 * p], b1v = bs[chg * 8 + 2 * p + 1];
#pragma unroll
        for (int j = 0; j < 4; j++) {
            float2 f = upk2(acc2[p][j]);
            pkv[2 * p][j] = __half_as_ushort(__float2half(fmaxf(f.x + b0v, 0.f)));
            pkv[2 * p + 1][j] = __half_as_ushort(__float2half(fmaxf(f.y + b1v, 0.f)));
        }
    }
    for (int c = 0; c < 4; c++) {
        if (pg >= c * 25 && pg < c * 25 + 25) {
            int pl = p0 - c * 100;
#pragma unroll
            for (int ch = 0; ch < 8; ch++)
#pragma unroll
                for (int j = 0; j < 4; j++)
                    spk[(pl + j) * 32 + chg * 8 + ch] = pkv[ch][j];
        }
        __syncthreads();
        for (int e = t; e < 3200; e += 400) {
            int pl = e >> 5, ch = e & 31;
            g_hh[(b * 400 + c * 100 + pl) * 256 + c0 + ch] = __ushort_as_half(spk[e]);
        }
        __syncthreads();
    }
}

// ---------------- K2: primary-caps conv, single-term fp16, K=128/stage -------------
// grid (2 co-halves of 128, 64 b-groups of 4), 256 thr = 8 warps (4M x 2N).
static constexpr int PRIM_NS2 = 162;

__global__ __launch_bounds__(256, 1) void k_prim(const float* __restrict__ pb) {
    extern __shared__ char sm[];
    uint32_t sb = smem_to_u32(sm);
    const int t = threadIdx.x, wid = t >> 5, lane = t & 31;
    const int co0 = blockIdx.x * 128;
    const int b0 = blockIdx.y * 4;
    const int warpM = wid >> 1, warpN = wid & 1;

    const uint32_t BUF[2] = {0u, 69632u};

    uint32_t a_sm[4]; long a_g[4];
#pragma unroll
    for (int k = 0; k < 4; k++) {
        int e = t + k * 256, row = e >> 3, q = e & 7;
        a_sm[k] = SWZ((uint32_t)(row * 128 + q * 16));
        a_g[k] = (long)(co0 + row) * 256 + q * 8;
    }
    uint32_t b_sm[5]; long b_g[5]; bool b_p[5];
#pragma unroll
    for (int k = 0; k < 5; k++) {
        int e = t + k * 256;
        b_p[k] = (e < 1152);
        int n = e >> 3, q = e & 7;
        if (!b_p[k]) { n = 0; q = 0; }
        int bb = n / 36, sp = n % 36, oy = sp / 6, ox = sp % 6;
        b_sm[k] = SWZ((uint32_t)(n * 128 + q * 16));
        b_g[k] = (long)((b0 + bb) * 400 + oy * 40 + ox * 2) * 256 + q * 8;
    }

    auto stage = [&](int buf, int s) {
        int tap = s >> 1, cb0 = (s & 1) * 2;
        uint32_t base = sb + BUF[buf];
#pragma unroll
        for (int h = 0; h < 2; h++) {
            int cb = cb0 + h;
            long wofs = (long)tap * 65536 + cb * 64;
            long xofs = (long)((tap / 9) * 20 + (tap % 9)) * 256 + cb * 64;
            uint32_t ah = base + h * 16384u;
            uint32_t bh = base + 32768u + h * 18432u;
#pragma unroll
            for (int k = 0; k < 4; k++)
                cpa16(ah + a_sm[k], g_whi + wofs + a_g[k]);
#pragma unroll
            for (int k = 0; k < 5; k++)
                if (b_p[k]) cpa16(bh + b_sm[k], g_hh + xofs + b_g[k]);
        }
        CP_COMMIT();
    };

    float acc[2][9][4];
#pragma unroll
    for (int mt = 0; mt < 2; mt++)
#pragma unroll
        for (int nt = 0; nt < 9; nt++)
#pragma unroll
            for (int j = 0; j < 4; j++) acc[mt][nt][j] = 0.f;

    const int arow = warpM * 32 + (lane & 15);
    const int n0w = warpN * 72;
    const int csel = (lane >> 4) * 16;

    uint32_t ahf[2][2][4], bhf[2][9][2];

    stage(0, 0);
    CP_WAIT0();
    __syncthreads();

    for (int s = 0; s < PRIM_NS2; s++) {
        int cur = s & 1;
        if (s + 1 < PRIM_NS2) stage(cur ^ 1, s + 1);

        uint32_t base = sb + BUF[cur];

#define LOADFRAG(PB, KS, AHB, BHB) do { \
        int kb_ = (KS) * 32; \
        uint32_t oa0_ = SWZ((uint32_t)(arow * 128 + kb_ + csel)); \
        uint32_t oa1_ = SWZ((uint32_t)((arow + 16) * 128 + kb_ + csel)); \
        ldm_x4(ahf[PB][0][0], ahf[PB][0][1], ahf[PB][0][2], ahf[PB][0][3], (AHB) + oa0_); \
        ldm_x4(ahf[PB][1][0], ahf[PB][1][1], ahf[PB][1][2], ahf[PB][1][3], (AHB) + oa1_); \
        _Pragma("unroll") \
        for (int p_ = 0; p_ < 4; p_++) { \
            uint32_t ob_ = SWZ((uint32_t)((n0w + p_ * 16 + (lane & 15)) * 128 + kb_ + csel)); \
            ldm_x4(bhf[PB][2 * p_][0], bhf[PB][2 * p_ + 1][0], \
                   bhf[PB][2 * p_][1], bhf[PB][2 * p_ + 1][1], (BHB) + ob_); \
        } \
        { uint32_t ob2_ = SWZ((uint32_t)((n0w + 64 + (lane & 7)) * 128 + kb_ + \
                                         ((lane >> 3) & 1) * 16)); \
          ldm_x2(bhf[PB][8][0], bhf[PB][8][1], (BHB) + ob2_); } \
    } while (0)

#pragma unroll
        for (int h = 0; h < 2; h++) {
            uint32_t AHB = base + h * 16384u;
            uint32_t BHB = base + 32768u + h * 18432u;
            LOADFRAG(0, 0, AHB, BHB);
#pragma unroll
            for (int ks = 0; ks < 4; ks++) {
                if (ks == 0) LOADFRAG(1, 1, AHB, BHB);
                else if (ks == 1) LOADFRAG(0, 2, AHB, BHB);
                else if (ks == 2) LOADFRAG(1, 3, AHB, BHB);
                const int fb = ks & 1;
#pragma unroll
                for (int mt = 0; mt < 2; mt++)
#pragma unroll
                    for (int nt = 0; nt < 9; nt++)
                        mma_f16(acc[mt][nt], ahf[fb][mt], bhf[fb][nt]);
            }
        }
#undef LOADFRAG
        if (s + 1 < PRIM_NS2) { CP_WAIT0(); }
        __syncthreads();
    }

    int atom = lane >> 2;
#pragma unroll
    for (int mt = 0; mt < 2; mt++) {
        int cobase = co0 + warpM * 32 + mt * 16;
        float bv0 = pb[cobase + atom];
        float bv1 = pb[cobase + 8 + atom];
        int cap0 = (cobase >> 3);
#pragma unroll
        for (int nt = 0; nt < 9; nt++) {
            float pr0 = acc[mt][nt][0] * (1.f / 32.f) + bv0;
            float pr1 = acc[mt][nt][1] * (1.f / 32.f) + bv0;
            float pr2 = acc[mt][nt][2] * (1.f / 32.f) + bv1;
            float pr3 = acc[mt][nt][3] * (1.f / 32.f) + bv1;
            float s0 = pr0 * pr0, s1 = pr1 * pr1, s2 = pr2 * pr2, s3 = pr3 * pr3;
#pragma unroll
            for (int d = 4; d <= 16; d <<= 1) {
                s0 += __shfl_xor_sync(0xffffffffu, s0, d);
                s1 += __shfl_xor_sync(0xffffffffu, s1, d);
                s2 += __shfl_xor_sync(0xffffffffu, s2, d);
                s3 += __shfl_xor_sync(0xffffffffu, s3, d);
            }
            float c0 = (s0 / (1.f + s0)) * rsqrtf(s0 + 1e-9f);
            float c1 = (s1 / (1.f + s1)) * rsqrtf(s1 + 1e-9f);
            float c2 = (s2 / (1.f + s2)) * rsqrtf(s2 + 1e-9f);
            float c3 = (s3 / (1.f + s3)) * rsqrtf(s3 + 1e-9f);
            int ncol = n0w + nt * 8 + (lane & 3) * 2;
            int bb = b0 + ncol / 36, sp = ncol % 36;
            float* base2 = g_x3 + bb * 9216;
            base2[(cap0 * 36 + sp) * 8 + atom] = pr0 * c0;
            base2[(cap0 * 36 + sp + 1) * 8 + atom] = pr1 * c1;
            base2[((cap0 + 1) * 36 + sp) * 8 + atom] = pr2 * c2;
            base2[((cap0 + 1) * 36 + sp + 1) * 8 + atom] = pr3 * c3;
        }
    }
}

// ---------------- K3: votes [i][b][ot] fp16, block per i ---------------------------
__global__ __launch_bounds__(256) void k_votes(const float* __restrict__ dw) {
    int i = blockIdx.x, t = threadIdx.x;    // t = b
    __shared__ float ws[1280];
    __shared__ float stg[256 * 17];
    for (int e = t; e < 1280; e += 256) ws[e] = dw[i * 1280 + e];
    const float4* xp = (const float4*)(g_x3 + t * 9216 + i * 8);
    float4 a0 = xp[0], a1 = xp[1];
    float xv[8] = {a0.x, a0.y, a0.z, a0.w, a1.x, a1.y, a1.z, a1.w};
    unsigned long long xpk[8];
#pragma unroll
    for (int a = 0; a < 8; a++) xpk[a] = pk2(xv[a], xv[a]);
    __syncthreads();
    __half2* orow2 = (__half2*)(g_votes + (long)i * 40960);
    for (int c = 0; c < 160; c += 16) {
        unsigned long long acc[8];
#pragma unroll
        for (int g = 0; g < 8; g++) acc[g] = 0ull;
#pragma unroll
        for (int a = 0; a < 8; a++) {
            const float2* wp = (const float2*)(ws + a * 160 + c);
#pragma unroll
            for (int g = 0; g < 8; g++) {
                float2 wv = wp[g];
                fma2(acc[g], xpk[a], pk2(wv.x, wv.y));
            }
        }
#pragma unroll
        for (int g = 0; g < 8; g++) {
            float2 f = upk2(acc[g]);
            stg[t * 17 + 2 * g] = f.x;
            stg[t * 17 + 2 * g + 1] = f.y;
        }
        __syncthreads();
        for (int e = t; e < 2048; e += 256) {
            int b = e >> 3, j = e & 7;
            orow2[b * 80 + (c >> 1) + j] =
                __floats2half2_rn(stg[b * 17 + 2 * j], stg[b * 17 + 2 * j + 1]);
        }
        __syncthreads();
    }
}

// ---------------- K4: fused 3-iteration routing (fp16 votes) -----------------------
__global__ __launch_bounds__(512) void k_route(const float* __restrict__ db,
                                               float* __restrict__ out_digit) {
    int b = blockIdx.x, t = threadIdx.x;
    int w = t >> 5, l = t & 31;
    __shared__ float act[160], asum[160], pre[160];
    __shared__ float red[16 * 160];
    const __half* V = g_votes + b * 160;

    {
        float p0[5] = {0.f, 0.f, 0.f, 0.f, 0.f};
        for (int i = w; i < 1152; i += 16) {
            const __half* vp = V + (long)i * 40960;
#pragma unroll
            for (int k = 0; k < 5; k++) p0[k] += __half2float(vp[32 * k + l]);
        }
#pragma unroll
        for (int k = 0; k < 5; k++) red[w * 160 + 32 * k + l] = p0[k];
    }
    __syncthreads();
    if (t < 160) {
        float s = 0.f;
#pragma unroll
        for (int ww = 0; ww < 16; ww++) s += red[ww * 160 + t];
        pre[t] = 0.1f * s + db[t];
    }
    __syncthreads();
    if (t < 160) {
        int o = t >> 4;
        float n2 = 0.f;
#pragma unroll
        for (int k = 0; k < 16; k++) { float v = pre[o * 16 + k]; n2 = fmaf(v, v, n2); }
        float a = pre[t] * (n2 / (1.f + n2)) * rsqrtf(n2 + 1e-9f);
        act[t] = a; asum[t] = a;
    }
    __syncthreads();

    for (int pass = 1; pass <= 2; pass++) {
        float pacc[5] = {0.f, 0.f, 0.f, 0.f, 0.f};
        for (int i = w; i < 1152; i += 16) {
            const __half* vp = V + (long)i * 40960;
            float v[5], d[5];
#pragma unroll
            for (int k = 0; k < 5; k++) v[k] = __half2float(vp[32 * k + l]);
#pragma unroll
            for (int k = 0; k < 5; k++) {
                float s = v[k] * asum[32 * k + l];
                s += __shfl_xor_sync(0xffffffffu, s, 1);
                s += __shfl_xor_sync(0xffffffffu, s, 2);
                s += __shfl_xor_sync(0xffffffffu, s, 4);
                s += __shfl_xor_sync(0xffffffffu, s, 8);
                d[k] = s;
            }
            float dn[5];
#pragma unroll
            for (int k = 0; k < 5; k++) dn[k] = __shfl_xor_sync(0xffffffffu, d[k], 16);
            float m = -1e30f;
#pragma unroll
            for (int k = 0; k < 5; k++) m = fmaxf(m, fmaxf(d[k], dn[k]));
            float sum = 0.f, e[5];
#pragma unroll
            for (int k = 0; k < 5; k++) {
                e[k] = __expf(d[k] - m); sum += e[k];
                sum += __expf(dn[k] - m);
            }
            float inv = 1.f / sum;
#pragma unroll
            for (int k = 0; k < 5; k++) pacc[k] = fmaf(e[k] * inv, v[k], pacc[k]);
        }
#pragma unroll
        for (int k = 0; k < 5; k++) red[w * 160 + 32 * k + l] = pacc[k];
        __syncthreads();
        if (t < 160) {
            float s = 0.f;
#pragma unroll
            for (int ww = 0; ww < 16; ww++) s += red[ww * 160 + t];
            pre[t] = s + db[t];
        }
        __syncthreads();
        if (t < 160) {
            int o = t >> 4;
            float n2 = 0.f;
#pragma unroll
            for (int k = 0; k < 16; k++) { float v = pre[o * 16 + k]; n2 = fmaf(v, v, n2); }
            float a = pre[t] * (n2 / (1.f + n2)) * rsqrtf(n2 + 1e-9f);
            act[t] = a;
            if (pass == 1) asum[t] += a;
        }
        __syncthreads();
    }
    if (t < 160) out_digit[b * 160 + t] = act[t];
}

// ---------------- K5: reconstruction MLP -------------------------------------------
__global__ __launch_bounds__(512) void k_fc1(const float* __restrict__ w1,
                                             const float* __restrict__ b1,
                                             const float* __restrict__ y,
                                             const float* __restrict__ digit) {
    int b0 = blockIdx.x * 2, t = threadIdx.x;
    __shared__ float m[2][160];
    if (t < 160) m[0][t] = digit[b0 * 160 + t] * y[b0 * 10 + (t >> 4)];
    else if (t >= 256 && t < 416) {
        int tt = t - 256;
        m[1][tt] = digit[(b0 + 1) * 160 + tt] * y[(b0 + 1) * 10 + (tt >> 4)];
    }
    __syncthreads();
    float a0 = b1[t], a1 = a0;
#pragma unroll 8
    for (int k = 0; k < 160; k++) {
        float wv = w1[k * 512 + t];
        a0 = fmaf(m[0][k], wv, a0);
        a1 = fmaf(m[1][k], wv, a1);
    }
    g_r1[b0 * 512 + t] = fmaxf(a0, 0.f);
    g_r1[(b0 + 1) * 512 + t] = fmaxf(a1, 0.f);
}

// fc2: grid (2 output-halves x 64 b-groups of 4), 512 threads.
__global__ __launch_bounds__(512) void k_fc2(const float* __restrict__ w2,
                                             const float* __restrict__ b2) {
    int nh = blockIdx.x & 1;
    int b0 = (blockIdx.x >> 1) * 4;
    int t = threadIdx.x;
    int o = nh * 512 + t;
    __shared__ float m[4][512];
    for (int e = t; e < 2048; e += 512)
        m[e >> 9][e & 511] = g_r1[(b0 + (e >> 9)) * 512 + (e & 511)];
    __syncthreads();
    float bb = b2[o];
    float a0 = bb, a1 = bb, a2 = bb, a3 = bb;
#pragma unroll 8
    for (int k = 0; k < 512; k++) {
        float wv = w2[k * 1024 + o];
        a0 = fmaf(m[0][k], wv, a0);
        a1 = fmaf(m[1][k], wv, a1);
        a2 = fmaf(m[2][k], wv, a2);
        a3 = fmaf(m[3][k], wv, a3);
    }
    g_r2[b0 * 1024 + o] = fmaxf(a0, 0.f);
    g_r2[(b0 + 1) * 1024 + o] = fmaxf(a1, 0.f);
    g_r2[(b0 + 2) * 1024 + o] = fmaxf(a2, 0.f);
    g_r2[(b0 + 3) * 1024 + o] = fmaxf(a3, 0.f);
}

// fc3: grid (2 output-halves x 64 b-groups of 4), 392 threads.
__global__ __launch_bounds__(392) void k_fc3(const float* __restrict__ w3,
                                             const float* __restrict__ b3,
                                             float* __restrict__ recon) {
    int nh = blockIdx.x & 1;
    int b0 = (blockIdx.x >> 1) * 4;
    int t = threadIdx.x;
    int o = nh * 392 + t;
    __shared__ float m[4][1024];
    for (int e = t; e < 4096; e += 392)
        m[e >> 10][e & 1023] = g_r2[(b0 + (e >> 10)) * 1024 + (e & 1023)];
    __syncthreads();
    float bb = b3[o];
    float a0 = bb, a1 = bb, a2 = bb, a3 = bb;
#pragma unroll 8
    for (int k = 0; k < 1024; k++) {
        float wv = w3[k * 784 + o];
        a0 = fmaf(m[0][k], wv, a0);
        a1 = fmaf(m[1][k], wv, a1);
        a2 = fmaf(m[2][k], wv, a2);
        a3 = fmaf(m[3][k], wv, a3);
    }
    recon[b0 * 784 + o] = 1.f / (1.f + __expf(-a0));
    recon[(b0 + 1) * 784 + o] = 1.f / (1.f + __expf(-a1));
    recon[(b0 + 2) * 784 + o] = 1.f / (1.f + __expf(-a2));
    recon[(b0 + 3) * 784 + o] = 1.f / (1.f + __expf(-a3));
}

// ---------------- launch ------------------------------------------------------------
extern "C" void kernel_launch(void* const* d_in, const int* in_sizes, int n_in,
                              void* d_out, int out_size) {
    const float* x   = (const float*)d_in[0];
    const float* y   = (const float*)d_in[1];
    const float* c1w = (const float*)d_in[2];
    const float* c1b = (const float*)d_in[3];
    const float* pw  = (const float*)d_in[4];
    const float* pb  = (const float*)d_in[5];
    const float* dw  = (const float*)d_in[6];
    const float* db  = (const float*)d_in[7];
    const float* w1  = (const float*)d_in[8];
    const float* b1  = (const float*)d_in[9];
    const float* w2  = (const float*)d_in[10];
    const float* b2  = (const float*)d_in[11];
    const float* w3  = (const float*)d_in[12];
    const float* b3  = (const float*)d_in[13];
    float* out = (float*)d_out;   // digit [0,40960), recon [40960,241664)

    cudaFuncSetAttribute(k_prim, cudaFuncAttributeMaxDynamicSharedMemorySize, 139264);
    cudaFuncSetAttribute(k_pre, cudaFuncAttributeMaxDynamicSharedMemorySize, 41472);

    k_pre<<<2304, 400, 41472>>>(pw, x, c1w, c1b);
    k_prim<<<dim3(2, 64), 256, 139264>>>(pb);
    k_votes<<<1152, 256>>>(dw);
    k_route<<<256, 512>>>(db, out);
    k_fc1<<<128, 512>>>(w1, b1, y, out);
    k_fc2<<<128, 512>>>(w2, b2);
    k_fc3<<<128, 392>>>(w3, b3, out + 40960);
}

// round 17
// speedup vs baseline: 1.5476x; 1.0872x over previous
#include <cuda_runtime.h>
#include <cuda_fp16.h>
#include <math.h>
#include <stdint.h>

// ---------------- scratch (device globals) ---------------------------------------
__device__ __half g_hh[26214400];          // conv1 out fp16, [b][pos400][ci256]
__device__ __half g_whi[5308416];          // prim weights fp16, [tap81][co256][ci256]
__device__ float g_x3[256 * 1152 * 8];     // squashed primary caps [b][i][a]
__device__ __half g_votes[47185920];       // votes fp16 [i][b][ot]
__device__ float g_r1[256 * 512];
__device__ float g_r2[256 * 1024];

// ---------------- f32x2 helpers ---------------------------------------------------
__device__ __forceinline__ unsigned long long pk2(float lo, float hi) {
    unsigned long long r;
    asm("mov.b64 %0, {%1, %2};" : "=l"(r) : "f"(lo), "f"(hi));
    return r;
}
__device__ __forceinline__ void fma2(unsigned long long& d, unsigned long long a,
                                     unsigned long long b) {
    asm("fma.rn.f32x2 %0, %1, %2, %0;" : "+l"(d) : "l"(a), "l"(b));
}
__device__ __forceinline__ float2 upk2(unsigned long long v) {
    float2 f;
    asm("mov.b64 {%0, %1}, %2;" : "=f"(f.x), "=f"(f.y) : "l"(v));
    return f;
}

// ---------------- baseline-PTX helpers --------------------------------------------
__device__ __forceinline__ uint32_t smem_to_u32(const void* p) {
    uint32_t a;
    asm("{ .reg .u64 t; cvta.to.shared.u64 t, %1; cvt.u32.u64 %0, t; }" : "=r"(a) : "l"(p));
    return a;
}
__device__ __forceinline__ void cpa16(uint32_t s, const void* g) {
    asm volatile("cp.async.cg.shared.global [%0], [%1], 16;" :: "r"(s), "l"(g));
}
#define CP_COMMIT() asm volatile("cp.async.commit_group;" ::: "memory")
#define CP_WAIT0()  asm volatile("cp.async.wait_group 0;" ::: "memory")

__device__ __forceinline__ void ldm_x4(uint32_t& r0, uint32_t& r1, uint32_t& r2,
                                       uint32_t& r3, uint32_t a) {
    asm volatile("ldmatrix.sync.aligned.m8n8.x4.shared.b16 {%0,%1,%2,%3}, [%4];"
                 : "=r"(r0), "=r"(r1), "=r"(r2), "=r"(r3) : "r"(a));
}
__device__ __forceinline__ void ldm_x2(uint32_t& r0, uint32_t& r1, uint32_t a) {
    asm volatile("ldmatrix.sync.aligned.m8n8.x2.shared.b16 {%0,%1}, [%2];"
                 : "=r"(r0), "=r"(r1) : "r"(a));
}
__device__ __forceinline__ void mma_f16(float* c, const uint32_t* a, const uint32_t* b) {
    asm volatile("mma.sync.aligned.m16n8k16.row.col.f32.f16.f16.f32 "
                 "{%0,%1,%2,%3}, {%4,%5,%6,%7}, {%8,%9}, {%0,%1,%2,%3};"
                 : "+f"(c[0]), "+f"(c[1]), "+f"(c[2]), "+f"(c[3])
                 : "r"(a[0]), "r"(a[1]), "r"(a[2]), "r"(a[3]), "r"(b[0]), "r"(b[1]));
}
#define SWZ(x) ((x) ^ (((x) >> 3) & 0x70))

// ---------------- K1: fused (wsplit | conv1) ---------------------------------------
__global__ __launch_bounds__(400) void k_pre(const float* __restrict__ pw,
                                             const float* __restrict__ x,
                                             const float* __restrict__ w,
                                             const float* __restrict__ bias) {
    extern __shared__ char dsm[];
    int t = threadIdx.x;

    if (blockIdx.x < 256) {
        unsigned short* sbuf = (unsigned short*)dsm;
        int co = blockIdx.x;
        if (t < 256) {
            const float* src = pw + co * 20736 + t * 81;
#pragma unroll
            for (int tap = 0; tap < 81; tap++)
                sbuf[tap * 256 + t] = __half_as_ushort(__float2half(src[tap]));
        }
        __syncthreads();
        for (int e = t; e < 81 * 256; e += 400) {
            int tap = e >> 8, c2 = e & 255;
            g_whi[tap * 65536 + co * 256 + c2] = __ushort_as_half(sbuf[e]);
        }
        return;
    }

    int blk = blockIdx.x - 256;
    int b = blk >> 3, c0 = (blk & 7) * 32;
    float* img = (float*)dsm;
    float* ws = img + 784;
    float* bs = ws + 2592;
    unsigned short* spk = (unsigned short*)(bs + 32);

    for (int e = t; e < 784; e += 400) img[e] = x[b * 784 + e];
    for (int e = t; e < 2592; e += 400) ws[e] = w[c0 * 81 + e];
    if (t < 32) bs[t] = bias[c0 + t];
    __syncthreads();

    int pg = t % 100, chg = t / 100;
    int p0 = pg * 4;
    int oy = p0 / 20, ox0 = p0 % 20;

    unsigned long long acc2[4][4];
#pragma unroll
    for (int p = 0; p < 4; p++)
#pragma unroll
        for (int j = 0; j < 4; j++) acc2[p][j] = 0ull;

    for (int kh = 0; kh < 9; kh++) {
        const float* row = img + (oy + kh) * 28 + ox0;
        float xw[12];
#pragma unroll
        for (int i = 0; i < 12; i++) xw[i] = row[i];
#pragma unroll
        for (int kw = 0; kw < 9; kw++) {
            unsigned long long xp[4];
#pragma unroll
            for (int j = 0; j < 4; j++) xp[j] = pk2(xw[kw + j], xw[kw + j]);
#pragma unroll
            for (int p = 0; p < 4; p++) {
                unsigned long long wp = pk2(ws[(chg * 8 + 2 * p) * 81 + kh * 9 + kw],
                                            ws[(chg * 8 + 2 * p + 1) * 81 + kh * 9 + kw]);
#pragma unroll
                for (int j = 0; j < 4; j++) fma2(acc2[p][j], xp[j], wp);
            }
        }
    }

    unsigned short pkv[8][4];
#pragma unroll
    for (int p = 0; p < 4; p++) {
        float b0v = bs[chg * 8 + 2 * p], b1v = bs[chg * 8 + 2 * p + 1];
#pragma unroll
        for (int j = 0; j < 4; j++) {
            float2 f = upk2(acc2[p][j]);
            pkv[2 * p][j] = __half_as_ushort(__float2half(fmaxf(f.x + b0v, 0.f)));
            pkv[2 * p + 1][j] = __half_as_ushort(__float2half(fmaxf(f.y + b1v, 0.f)));
        }
    }
    for (int c = 0; c < 4; c++) {
        if (pg >= c * 25 && pg < c * 25 + 25) {
            int pl = p0 - c * 100;
#pragma unroll
            for (int ch = 0; ch < 8; ch++)
#pragma unroll
                for (int j = 0; j < 4; j++)
                    spk[(pl + j) * 32 + chg * 8 + ch] = pkv[ch][j];
        }
        __syncthreads();
        for (int e = t; e < 3200; e += 400) {
            int pl = e >> 5, ch = e & 31;
            g_hh[(b * 400 + c * 100 + pl) * 256 + c0 + ch] = __ushort_as_half(spk[e]);
        }
        __syncthreads();
    }
}

// ---------------- K2: primary-caps conv, single-term fp16, K=128/stage -------------
static constexpr int PRIM_NS2 = 162;

__global__ __launch_bounds__(256, 1) void k_prim(const float* __restrict__ pb) {
    extern __shared__ char sm[];
    uint32_t sb = smem_to_u32(sm);
    const int t = threadIdx.x, wid = t >> 5, lane = t & 31;
    const int co0 = blockIdx.x * 128;
    const int b0 = blockIdx.y * 4;
    const int warpM = wid >> 1, warpN = wid & 1;

    const uint32_t BUF[2] = {0u, 69632u};

    uint32_t a_sm[4]; long a_g[4];
#pragma unroll
    for (int k = 0; k < 4; k++) {
        int e = t + k * 256, row = e >> 3, q = e & 7;
        a_sm[k] = SWZ((uint32_t)(row * 128 + q * 16));
        a_g[k] = (long)(co0 + row) * 256 + q * 8;
    }
    uint32_t b_sm[5]; long b_g[5]; bool b_p[5];
#pragma unroll
    for (int k = 0; k < 5; k++) {
        int e = t + k * 256;
        b_p[k] = (e < 1152);
        int n = e >> 3, q = e & 7;
        if (!b_p[k]) { n = 0; q = 0; }
        int bb = n / 36, sp = n % 36, oy = sp / 6, ox = sp % 6;
        b_sm[k] = SWZ((uint32_t)(n * 128 + q * 16));
        b_g[k] = (long)((b0 + bb) * 400 + oy * 40 + ox * 2) * 256 + q * 8;
    }

    auto stage = [&](int buf, int s) {
        int tap = s >> 1, cb0 = (s & 1) * 2;
        uint32_t base = sb + BUF[buf];
#pragma unroll
        for (int h = 0; h < 2; h++) {
            int cb = cb0 + h;
            long wofs = (long)tap * 65536 + cb * 64;
            long xofs = (long)((tap / 9) * 20 + (tap % 9)) * 256 + cb * 64;
            uint32_t ah = base + h * 16384u;
            uint32_t bh = base + 32768u + h * 18432u;
#pragma unroll
            for (int k = 0; k < 4; k++)
                cpa16(ah + a_sm[k], g_whi + wofs + a_g[k]);
#pragma unroll
            for (int k = 0; k < 5; k++)
                if (b_p[k]) cpa16(bh + b_sm[k], g_hh + xofs + b_g[k]);
        }
        CP_COMMIT();
    };

    float acc[2][9][4];
#pragma unroll
    for (int mt = 0; mt < 2; mt++)
#pragma unroll
        for (int nt = 0; nt < 9; nt++)
#pragma unroll
            for (int j = 0; j < 4; j++) acc[mt][nt][j] = 0.f;

    const int arow = warpM * 32 + (lane & 15);
    const int n0w = warpN * 72;
    const int csel = (lane >> 4) * 16;

    uint32_t ahf[2][2][4], bhf[2][9][2];

    stage(0, 0);
    CP_WAIT0();
    __syncthreads();

    for (int s = 0; s < PRIM_NS2; s++) {
        int cur = s & 1;
        if (s + 1 < PRIM_NS2) stage(cur ^ 1, s + 1);

        uint32_t base = sb + BUF[cur];

#define LOADFRAG(PB, KS, AHB, BHB) do { \
        int kb_ = (KS) * 32; \
        uint32_t oa0_ = SWZ((uint32_t)(arow * 128 + kb_ + csel)); \
        uint32_t oa1_ = SWZ((uint32_t)((arow + 16) * 128 + kb_ + csel)); \
        ldm_x4(ahf[PB][0][0], ahf[PB][0][1], ahf[PB][0][2], ahf[PB][0][3], (AHB) + oa0_); \
        ldm_x4(ahf[PB][1][0], ahf[PB][1][1], ahf[PB][1][2], ahf[PB][1][3], (AHB) + oa1_); \
        _Pragma("unroll") \
        for (int p_ = 0; p_ < 4; p_++) { \
            uint32_t ob_ = SWZ((uint32_t)((n0w + p_ * 16 + (lane & 15)) * 128 + kb_ + csel)); \
            ldm_x4(bhf[PB][2 * p_][0], bhf[PB][2 * p_ + 1][0], \
                   bhf[PB][2 * p_][1], bhf[PB][2 * p_ + 1][1], (BHB) + ob_); \
        } \
        { uint32_t ob2_ = SWZ((uint32_t)((n0w + 64 + (lane & 7)) * 128 + kb_ + \
                                         ((lane >> 3) & 1) * 16)); \
          ldm_x2(bhf[PB][8][0], bhf[PB][8][1], (BHB) + ob2_); } \
    } while (0)

#pragma unroll
        for (int h = 0; h < 2; h++) {
            uint32_t AHB = base + h * 16384u;
            uint32_t BHB = base + 32768u + h * 18432u;
            LOADFRAG(0, 0, AHB, BHB);
#pragma unroll
            for (int ks = 0; ks < 4; ks++) {
                if (ks == 0) LOADFRAG(1, 1, AHB, BHB);
                else if (ks == 1) LOADFRAG(0, 2, AHB, BHB);
                else if (ks == 2) LOADFRAG(1, 3, AHB, BHB);
                const int fb = ks & 1;
#pragma unroll
                for (int mt = 0; mt < 2; mt++)
#pragma unroll
                    for (int nt = 0; nt < 9; nt++)
                        mma_f16(acc[mt][nt], ahf[fb][mt], bhf[fb][nt]);
            }
        }
#undef LOADFRAG
        if (s + 1 < PRIM_NS2) { CP_WAIT0(); }
        __syncthreads();
    }

    int atom = lane >> 2;
#pragma unroll
    for (int mt = 0; mt < 2; mt++) {
        int cobase = co0 + warpM * 32 + mt * 16;
        float bv0 = pb[cobase + atom];
        float bv1 = pb[cobase + 8 + atom];
        int cap0 = (cobase >> 3);
#pragma unroll
        for (int nt = 0; nt < 9; nt++) {
            float pr0 = acc[mt][nt][0] * (1.f / 32.f) + bv0;
            float pr1 = acc[mt][nt][1] * (1.f / 32.f) + bv0;
            float pr2 = acc[mt][nt][2] * (1.f / 32.f) + bv1;
            float pr3 = acc[mt][nt][3] * (1.f / 32.f) + bv1;
            float s0 = pr0 * pr0, s1 = pr1 * pr1, s2 = pr2 * pr2, s3 = pr3 * pr3;
#pragma unroll
            for (int d = 4; d <= 16; d <<= 1) {
                s0 += __shfl_xor_sync(0xffffffffu, s0, d);
                s1 += __shfl_xor_sync(0xffffffffu, s1, d);
                s2 += __shfl_xor_sync(0xffffffffu, s2, d);
                s3 += __shfl_xor_sync(0xffffffffu, s3, d);
            }
            float c0 = (s0 / (1.f + s0)) * rsqrtf(s0 + 1e-9f);
            float c1 = (s1 / (1.f + s1)) * rsqrtf(s1 + 1e-9f);
            float c2 = (s2 / (1.f + s2)) * rsqrtf(s2 + 1e-9f);
            float c3 = (s3 / (1.f + s3)) * rsqrtf(s3 + 1e-9f);
            int ncol = n0w + nt * 8 + (lane & 3) * 2;
            int bb = b0 + ncol / 36, sp = ncol % 36;
            float* base2 = g_x3 + bb * 9216;
            base2[(cap0 * 36 + sp) * 8 + atom] = pr0 * c0;
            base2[(cap0 * 36 + sp + 1) * 8 + atom] = pr1 * c1;
            base2[((cap0 + 1) * 36 + sp) * 8 + atom] = pr2 * c2;
            base2[((cap0 + 1) * 36 + sp + 1) * 8 + atom] = pr3 * c3;
        }
    }
}

// ---------------- K3: votes [i][b][ot] fp16, block per i ---------------------------
__global__ __launch_bounds__(256) void k_votes(const float* __restrict__ dw) {
    int i = blockIdx.x, t = threadIdx.x;    // t = b
    __shared__ float ws[1280];
    __shared__ float stg[256 * 17];
    for (int e = t; e < 1280; e += 256) ws[e] = dw[i * 1280 + e];
    const float4* xp = (const float4*)(g_x3 + t * 9216 + i * 8);
    float4 a0 = xp[0], a1 = xp[1];
    float xv[8] = {a0.x, a0.y, a0.z, a0.w, a1.x, a1.y, a1.z, a1.w};
    unsigned long long xpk[8];
#pragma unroll
    for (int a = 0; a < 8; a++) xpk[a] = pk2(xv[a], xv[a]);
    __syncthreads();
    __half2* orow2 = (__half2*)(g_votes + (long)i * 40960);
    for (int c = 0; c < 160; c += 16) {
        unsigned long long acc[8];
#pragma unroll
        for (int g = 0; g < 8; g++) acc[g] = 0ull;
#pragma unroll
        for (int a = 0; a < 8; a++) {
            const float2* wp = (const float2*)(ws + a * 160 + c);
#pragma unroll
            for (int g = 0; g < 8; g++) {
                float2 wv = wp[g];
                fma2(acc[g], xpk[a], pk2(wv.x, wv.y));
            }
        }
#pragma unroll
        for (int g = 0; g < 8; g++) {
            float2 f = upk2(acc[g]);
            stg[t * 17 + 2 * g] = f.x;
            stg[t * 17 + 2 * g + 1] = f.y;
        }
        __syncthreads();
        for (int e = t; e < 2048; e += 256) {
            int b = e >> 3, j = e & 7;
            orow2[b * 80 + (c >> 1) + j] =
                __floats2half2_rn(stg[b * 17 + 2 * j], stg[b * 17 + 2 * j + 1]);
        }
        __syncthreads();
    }
}

// ---------------- K4: fused routing, group-per-i (8 shfl/i) ------------------------
// 512 thr = 32 groups of 16 lanes; group owns one i per iteration; lane j<10 owns
// class o=j: private 16-FMA logit dot + register pacc. Butterfly softmax over 16.
__global__ __launch_bounds__(512) void k_route(const float* __restrict__ db,
                                               float* __restrict__ out_digit) {
    int b = blockIdx.x, t = threadIdx.x;
    int grp = t >> 4, j = t & 15;
    bool on = (j < 10);
    __shared__ float act[160], asum[160], pre[160];
    __shared__ float red[32 * 160];
    const __half* V = g_votes + b * 160;
    const long JOFS = j < 10 ? j * 16 : 0;

    // ---- pass 0: pre = 0.1 * sum_i votes + bias ----
    {
        float pacc[16];
#pragma unroll
        for (int k = 0; k < 16; k++) pacc[k] = 0.f;
        for (int i = grp; i < 1152; i += 32) {
            if (on) {
                const uint4* vp = (const uint4*)(V + (long)i * 40960 + JOFS);
                uint4 u0 = vp[0], u1 = vp[1];
                const __half2* h0 = (const __half2*)&u0;
                const __half2* h1 = (const __half2*)&u1;
#pragma unroll
                for (int k = 0; k < 4; k++) {
                    float2 f0 = __half22float2(h0[k]);
                    float2 f1 = __half22float2(h1[k]);
                    pacc[2 * k] += f0.x; pacc[2 * k + 1] += f0.y;
                    pacc[8 + 2 * k] += f1.x; pacc[9 + 2 * k] += f1.y;
                }
            }
        }
        if (on)
#pragma unroll
            for (int k = 0; k < 16; k++) red[grp * 160 + j * 16 + k] = pacc[k];
    }
    __syncthreads();
    if (t < 160) {
        float s = 0.f;
#pragma unroll
        for (int g = 0; g < 32; g++) s += red[g * 160 + t];
        pre[t] = 0.1f * s + db[t];
    }
    __syncthreads();
    if (t < 160) {
        int o = t >> 4;
        float n2 = 0.f;
#pragma unroll
        for (int k = 0; k < 16; k++) { float v = pre[o * 16 + k]; n2 = fmaf(v, v, n2); }
        float a = pre[t] * (n2 / (1.f + n2)) * rsqrtf(n2 + 1e-9f);
        act[t] = a; asum[t] = a;
    }
    __syncthreads();

    for (int pass = 1; pass <= 2; pass++) {
        float areg[16];
        if (on)
#pragma unroll
            for (int k = 0; k < 16; k++) areg[k] = asum[j * 16 + k];
        float pacc[16];
#pragma unroll
        for (int k = 0; k < 16; k++) pacc[k] = 0.f;

        for (int i = grp; i < 1152; i += 32) {
            float v[16], d;
            if (on) {
                const uint4* vp = (const uint4*)(V + (long)i * 40960 + JOFS);
                uint4 u0 = vp[0], u1 = vp[1];
                const __half2* h0 = (const __half2*)&u0;
                const __half2* h1 = (const __half2*)&u1;
#pragma unroll
                for (int k = 0; k < 4; k++) {
                    float2 f0 = __half22float2(h0[k]);
                    float2 f1 = __half22float2(h1[k]);
                    v[2 * k] = f0.x; v[2 * k + 1] = f0.y;
                    v[8 + 2 * k] = f1.x; v[9 + 2 * k] = f1.y;
                }
                d = 0.f;
#pragma unroll
                for (int k = 0; k < 16; k++) d = fmaf(v[k], areg[k], d);
            } else d = -1e30f;
            float m = d;
#pragma unroll
            for (int del = 1; del < 16; del <<= 1)
                m = fmaxf(m, __shfl_xor_sync(0xffffffffu, m, del));
            float e = on ? __expf(d - m) : 0.f;
            float s = e;
#pragma unroll
            for (int del = 1; del < 16; del <<= 1)
                s += __shfl_xor_sync(0xffffffffu, s, del);
            if (on) {
                float r = e / s;
#pragma unroll
                for (int k = 0; k < 16; k++) pacc[k] = fmaf(r, v[k], pacc[k]);
            }
        }
        if (on)
#pragma unroll
            for (int k = 0; k < 16; k++) red[grp * 160 + j * 16 + k] = pacc[k];
        __syncthreads();
        if (t < 160) {
            float s = 0.f;
#pragma unroll
            for (int g = 0; g < 32; g++) s += red[g * 160 + t];
            pre[t] = s + db[t];
        }
        __syncthreads();
        if (t < 160) {
            int o = t >> 4;
            float n2 = 0.f;
#pragma unroll
            for (int k = 0; k < 16; k++) { float v = pre[o * 16 + k]; n2 = fmaf(v, v, n2); }
            float a = pre[t] * (n2 / (1.f + n2)) * rsqrtf(n2 + 1e-9f);
            act[t] = a;
            if (pass == 1) asum[t] += a;
        }
        __syncthreads();
    }
    if (t < 160) out_digit[b * 160 + t] = act[t];
}

// ---------------- K5: reconstruction MLP -------------------------------------------
__global__ __launch_bounds__(512) void k_fc1(const float* __restrict__ w1,
                                             const float* __restrict__ b1,
                                             const float* __restrict__ y,
                                             const float* __restrict__ digit) {
    int b0 = blockIdx.x * 2, t = threadIdx.x;
    __shared__ float m[2][160];
    if (t < 160) m[0][t] = digit[b0 * 160 + t] * y[b0 * 10 + (t >> 4)];
    else if (t >= 256 && t < 416) {
        int tt = t - 256;
        m[1][tt] = digit[(b0 + 1) * 160 + tt] * y[(b0 + 1) * 10 + (tt >> 4)];
    }
    __syncthreads();
    float a0 = b1[t], a1 = a0;
#pragma unroll 8
    for (int k = 0; k < 160; k++) {
        float wv = w1[k * 512 + t];
        a0 = fmaf(m[0][k], wv, a0);
        a1 = fmaf(m[1][k], wv, a1);
    }
    g_r1[b0 * 512 + t] = fmaxf(a0, 0.f);
    g_r1[(b0 + 1) * 512 + t] = fmaxf(a1, 0.f);
}

__global__ __launch_bounds__(512) void k_fc2(const float* __restrict__ w2,
                                             const float* __restrict__ b2) {
    int nh = blockIdx.x & 1;
    int b0 = (blockIdx.x >> 1) * 4;
    int t = threadIdx.x;
    int o = nh * 512 + t;
    __shared__ float m[4][512];
    for (int e = t; e < 2048; e += 512)
        m[e >> 9][e & 511] = g_r1[(b0 + (e >> 9)) * 512 + (e & 511)];
    __syncthreads();
    float bb = b2[o];
    float a0 = bb, a1 = bb, a2 = bb, a3 = bb;
#pragma unroll 8
    for (int k = 0; k < 512; k++) {
        float wv = w2[k * 1024 + o];
        a0 = fmaf(m[0][k], wv, a0);
        a1 = fmaf(m[1][k], wv, a1);
        a2 = fmaf(m[2][k], wv, a2);
        a3 = fmaf(m[3][k], wv, a3);
    }
    g_r2[b0 * 1024 + o] = fmaxf(a0, 0.f);
    g_r2[(b0 + 1) * 1024 + o] = fmaxf(a1, 0.f);
    g_r2[(b0 + 2) * 1024 + o] = fmaxf(a2, 0.f);
    g_r2[(b0 + 3) * 1024 + o] = fmaxf(a3, 0.f);
}

__global__ __launch_bounds__(392) void k_fc3(const float* __restrict__ w3,
                                             const float* __restrict__ b3,
                                             float* __restrict__ recon) {
    int nh = blockIdx.x & 1;
    int b0 = (blockIdx.x >> 1) * 4;
    int t = threadIdx.x;
    int o = nh * 392 + t;
    __shared__ float m[4][1024];
    for (int e = t; e < 4096; e += 392)
        m[e >> 10][e & 1023] = g_r2[(b0 + (e >> 10)) * 1024 + (e & 1023)];
    __syncthreads();
    float bb = b3[o];
    float a0 = bb, a1 = bb, a2 = bb, a3 = bb;
#pragma unroll 8
    for (int k = 0; k < 1024; k++) {
        float wv = w3[k * 784 + o];
        a0 = fmaf(m[0][k], wv, a0);
        a1 = fmaf(m[1][k], wv, a1);
        a2 = fmaf(m[2][k], wv, a2);
        a3 = fmaf(m[3][k], wv, a3);
    }
    recon[b0 * 784 + o] = 1.f / (1.f + __expf(-a0));
    recon[(b0 + 1) * 784 + o] = 1.f / (1.f + __expf(-a1));
    recon[(b0 + 2) * 784 + o] = 1.f / (1.f + __expf(-a2));
    recon[(b0 + 3) * 784 + o] = 1.f / (1.f + __expf(-a3));
}

// ---------------- launch ------------------------------------------------------------
extern "C" void kernel_launch(void* const* d_in, const int* in_sizes, int n_in,
                              void* d_out, int out_size) {
    const float* x   = (const float*)d_in[0];
    const float* y   = (const float*)d_in[1];
    const float* c1w = (const float*)d_in[2];
    const float* c1b = (const float*)d_in[3];
    const float* pw  = (const float*)d_in[4];
    const float* pb  = (const float*)d_in[5];
    const float* dw  = (const float*)d_in[6];
    const float* db  = (const float*)d_in[7];
    const float* w1  = (const float*)d_in[8];
    const float* b1  = (const float*)d_in[9];
    const float* w2  = (const float*)d_in[10];
    const float* b2  = (const float*)d_in[11];
    const float* w3  = (const float*)d_in[12];
    const float* b3  = (const float*)d_in[13];
    float* out = (float*)d_out;   // digit [0,40960), recon [40960,241664)

    cudaFuncSetAttribute(k_prim, cudaFuncAttributeMaxDynamicSharedMemorySize, 139264);
    cudaFuncSetAttribute(k_pre, cudaFuncAttributeMaxDynamicSharedMemorySize, 41472);

    k_pre<<<2304, 400, 41472>>>(pw, x, c1w, c1b);
    k_prim<<<dim3(2, 64), 256, 139264>>>(pb);
    k_votes<<<1152, 256>>>(dw);
    k_route<<<256, 512>>>(db, out);
    k_fc1<<<128, 512>>>(w1, b1, y, out);
    k_fc2<<<128, 512>>>(w2, b2);
    k_fc3<<<128, 392>>>(w3, b3, out + 40960);
}